// round 1
// baseline (speedup 1.0000x reference)
#include <cuda_runtime.h>
#include <cuda_bf16.h>
#include <math.h>

// ---------------- problem constants ----------------
#define BB 4
#define TT 2048
#define DD 1024
#define HH 8
#define DKk 128
#define DVv 256
#define CC 64
#define NCHUNK (TT / CC)   // 32
#define MROWS (BB * TT)    // 8192

// ---------------- scratch (no runtime allocation allowed) ----------------
__device__ float g_q[MROWS * HH * DKk];   //  8.4M floats
__device__ float g_k[MROWS * HH * DKk];
__device__ float g_v[MROWS * HH * DVv];   // 16.8M floats
__device__ float g_g[MROWS * HH * DVv];
__device__ float g_o[MROWS * HH * DVv];

// ---------------- fp32 SGEMM: C = A(MxK) @ B(KxN), row major, M%128==0, N%128==0, K%8==0 ----------------
__global__ __launch_bounds__(256) void sgemm128(const float* __restrict__ A,
                                                const float* __restrict__ B,
                                                float* __restrict__ Cm,
                                                int M, int N, int K) {
    const int BM = 128, BN = 128, BK = 8;
    __shared__ float As[BK][BM];
    __shared__ float Bs[BK][BN];

    const int tid  = threadIdx.x;
    const int brow = blockIdx.y * BM;
    const int bcol = blockIdx.x * BN;

    const int aRow = tid >> 1;          // 0..127
    const int aCol = (tid & 1) * 4;     // 0 or 4
    const int bRow = tid >> 5;          // 0..7
    const int bCol = (tid & 31) * 4;    // 0..124

    const int ty = tid >> 4;            // 0..15 -> rows ty*8..+8
    const int tx = tid & 15;            // 0..15 -> cols tx*8..+8

    float acc[8][8];
#pragma unroll
    for (int i = 0; i < 8; i++)
#pragma unroll
        for (int j = 0; j < 8; j++) acc[i][j] = 0.f;

    const float* Aptr = A + (size_t)(brow + aRow) * K + aCol;
    const float* Bptr = B + bcol + bCol;

    for (int k0 = 0; k0 < K; k0 += BK) {
        float4 a4 = *(const float4*)(Aptr + k0);
        As[aCol + 0][aRow] = a4.x;
        As[aCol + 1][aRow] = a4.y;
        As[aCol + 2][aRow] = a4.z;
        As[aCol + 3][aRow] = a4.w;
        float4 b4 = *(const float4*)(Bptr + (size_t)(k0 + bRow) * N);
        *(float4*)&Bs[bRow][bCol] = b4;
        __syncthreads();

#pragma unroll
        for (int kk = 0; kk < BK; kk++) {
            float ra[8], rb[8];
            *(float4*)&ra[0] = *(const float4*)&As[kk][ty * 8];
            *(float4*)&ra[4] = *(const float4*)&As[kk][ty * 8 + 4];
            *(float4*)&rb[0] = *(const float4*)&Bs[kk][tx * 8];
            *(float4*)&rb[4] = *(const float4*)&Bs[kk][tx * 8 + 4];
#pragma unroll
            for (int i = 0; i < 8; i++)
#pragma unroll
                for (int j = 0; j < 8; j++) acc[i][j] += ra[i] * rb[j];
        }
        __syncthreads();
    }

#pragma unroll
    for (int i = 0; i < 8; i++) {
        float* crow = Cm + (size_t)(brow + ty * 8 + i) * N + bcol + tx * 8;
        *(float4*)&crow[0] = make_float4(acc[i][0], acc[i][1], acc[i][2], acc[i][3]);
        *(float4*)&crow[4] = make_float4(acc[i][4], acc[i][5], acc[i][6], acc[i][7]);
    }
}

// ---------------- RoPE (in place on q and k), q also scaled by DK^-1/2 ----------------
__global__ void rope_kernel(float* __restrict__ q, float* __restrict__ k) {
    int idx = blockIdx.x * blockDim.x + threadIdx.x;
    const int total = BB * TT * HH * (DKk / 2);
    if (idx >= total) return;
    int i = idx & 63;                  // freq index 0..63
    int h = (idx >> 6) & (HH - 1);
    int t = (idx >> 9) & (TT - 1);
    int b = idx >> 20;

    float inv = powf(10000.f, -(float)i * (1.0f / 64.0f));
    float f = (float)t * inv;
    float s, c;
    sincosf(f, &s, &c);

    size_t base = ((((size_t)b * TT + t) * HH + h) << 7);  // *DK
    const float sc = 0.08838834764831845f;                  // 128^-0.5
    float q1 = q[base + i], q2 = q[base + 64 + i];
    q[base + i]      = (q1 * c - q2 * s) * sc;
    q[base + 64 + i] = (q2 * c + q1 * s) * sc;
    float k1 = k[base + i], k2 = k[base + 64 + i];
    k[base + i]      = k1 * c - k2 * s;
    k[base + 64 + i] = k2 * c + k1 * s;
}

// ---------------- chunked retention ----------------
// grid: (DV/64, H, B); block 256 threads. Each block owns a 64-wide DV slice.
// smem layout (floats):
//  S   : 128 x 65
//  qs  : 64 x 129
//  ks  : 64 x 129
//  vs  : 64 x 65
//  at  : 64 x 65
//  gpow/decq/deck : 64 each
#define RET_SMEM_FLOATS (128 * 65 + 2 * 64 * 129 + 2 * 64 * 65 + 3 * 64)

__global__ __launch_bounds__(256) void retention_kernel(const float* __restrict__ q,
                                                        const float* __restrict__ k,
                                                        const float* __restrict__ v,
                                                        float* __restrict__ o) {
    const int sl = blockIdx.x;   // DV slice 0..3
    const int h  = blockIdx.y;
    const int b  = blockIdx.z;
    const int tid = threadIdx.x;

    extern __shared__ float sm[];
    float* S    = sm;                       // 128*65
    float* qs   = S + 128 * 65;             // 64*129
    float* ks   = qs + 64 * 129;            // 64*129
    float* vs   = ks + 64 * 129;            // 64*65
    float* at   = vs + 64 * 65;             // 64*65
    float* gpow = at + 64 * 65;             // 64
    float* decq = gpow + 64;                // 64
    float* deck = decq + 64;                // 64

    const float gamma = 1.0f - exp2f(-5.0f - (float)h);
    if (tid < 64) {
        gpow[tid] = powf(gamma, (float)tid);
        decq[tid] = powf(gamma, (float)(tid + 1));
        deck[tid] = powf(gamma, (float)(63 - tid));
    }
    const float gC = powf(gamma, 64.0f);

    for (int e = tid; e < 128 * 65; e += 256) S[e] = 0.f;
    __syncthreads();

    const int ti = tid >> 4;    // 0..15
    const int te = tid & 15;    // 0..15

    for (int n = 0; n < NCHUNK; n++) {
        const int t0 = n * CC;
        // ---- loads ----
        for (int e = tid; e < 64 * 128; e += 256) {
            int i = e >> 7, dk = e & 127;
            size_t gi = ((((size_t)b * TT + t0 + i) * HH + h) << 7) + dk;
            qs[i * 129 + dk] = q[gi];
            ks[i * 129 + dk] = k[gi];
        }
        for (int e = tid; e < 64 * 64; e += 256) {
            int i = e >> 6, ev = e & 63;
            size_t gi = (((size_t)b * TT + t0 + i) * HH + h) * DVv + sl * 64 + ev;
            vs[i * 65 + ev] = v[gi];
        }
        __syncthreads();

        // ---- attn[i][j] = (q_i . k_j) * gamma^(i-j) for i>=j ----
        {
            float acc[4][4];
#pragma unroll
            for (int a = 0; a < 4; a++)
#pragma unroll
                for (int bq = 0; bq < 4; bq++) acc[a][bq] = 0.f;
            for (int dk = 0; dk < 128; dk++) {
                float ra[4], rb[4];
#pragma unroll
                for (int ii = 0; ii < 4; ii++) ra[ii] = qs[(ti * 4 + ii) * 129 + dk];
#pragma unroll
                for (int jj = 0; jj < 4; jj++) rb[jj] = ks[(te * 4 + jj) * 129 + dk];
#pragma unroll
                for (int ii = 0; ii < 4; ii++)
#pragma unroll
                    for (int jj = 0; jj < 4; jj++) acc[ii][jj] += ra[ii] * rb[jj];
            }
#pragma unroll
            for (int ii = 0; ii < 4; ii++)
#pragma unroll
                for (int jj = 0; jj < 4; jj++) {
                    int i = ti * 4 + ii, j = te * 4 + jj;
                    at[i * 65 + j] = (i >= j) ? acc[ii][jj] * gpow[i - j] : 0.f;
                }
        }
        __syncthreads();

        // ---- o = attn @ v  +  decq[i] * (q @ S) ----
        {
            float aI[4][4], aS[4][4];
#pragma unroll
            for (int a = 0; a < 4; a++)
#pragma unroll
                for (int bq = 0; bq < 4; bq++) { aI[a][bq] = 0.f; aS[a][bq] = 0.f; }
            for (int j = 0; j < 64; j++) {
                float ra[4], rb[4];
#pragma unroll
                for (int ii = 0; ii < 4; ii++) ra[ii] = at[(ti * 4 + ii) * 65 + j];
#pragma unroll
                for (int ee = 0; ee < 4; ee++) rb[ee] = vs[j * 65 + te * 4 + ee];
#pragma unroll
                for (int ii = 0; ii < 4; ii++)
#pragma unroll
                    for (int ee = 0; ee < 4; ee++) aI[ii][ee] += ra[ii] * rb[ee];
            }
            for (int dk = 0; dk < 128; dk++) {
                float ra[4], rb[4];
#pragma unroll
                for (int ii = 0; ii < 4; ii++) ra[ii] = qs[(ti * 4 + ii) * 129 + dk];
#pragma unroll
                for (int ee = 0; ee < 4; ee++) rb[ee] = S[dk * 65 + te * 4 + ee];
#pragma unroll
                for (int ii = 0; ii < 4; ii++)
#pragma unroll
                    for (int ee = 0; ee < 4; ee++) aS[ii][ee] += ra[ii] * rb[ee];
            }
#pragma unroll
            for (int ii = 0; ii < 4; ii++) {
                int i = ti * 4 + ii;
                float dq = decq[i];
                size_t base = (((size_t)b * TT + t0 + i) * HH + h) * DVv + sl * 64 + te * 4;
#pragma unroll
                for (int ee = 0; ee < 4; ee++)
                    o[base + ee] = aI[ii][ee] + dq * aS[ii][ee];
            }
        }
        __syncthreads();   // everyone done reading old S before update

        // ---- S = gC*S + (k*deck)^T @ v ----
        {
            float acc[8][4];
#pragma unroll
            for (int a = 0; a < 8; a++)
#pragma unroll
                for (int bq = 0; bq < 4; bq++) acc[a][bq] = 0.f;
            for (int j = 0; j < 64; j++) {
                float dkj = deck[j];
                float ra[8], rb[4];
#pragma unroll
                for (int dd = 0; dd < 8; dd++) ra[dd] = ks[j * 129 + ti * 8 + dd] * dkj;
#pragma unroll
                for (int ee = 0; ee < 4; ee++) rb[ee] = vs[j * 65 + te * 4 + ee];
#pragma unroll
                for (int dd = 0; dd < 8; dd++)
#pragma unroll
                    for (int ee = 0; ee < 4; ee++) acc[dd][ee] += ra[dd] * rb[ee];
            }
#pragma unroll
            for (int dd = 0; dd < 8; dd++)
#pragma unroll
                for (int ee = 0; ee < 4; ee++) {
                    int dk = ti * 8 + dd, ev = te * 4 + ee;
                    S[dk * 65 + ev] = gC * S[dk * 65 + ev] + acc[dd][ee];
                }
        }
        __syncthreads();   // S updated + tiles reusable
    }
}

// ---------------- RMSNorm over DV + swish gate, in place on o ----------------
__global__ __launch_bounds__(256) void normgate_kernel(float* __restrict__ o,
                                                       const float* __restrict__ g,
                                                       const float* __restrict__ norm_w) {
    int warp = (blockIdx.x * blockDim.x + threadIdx.x) >> 5;
    int lane = threadIdx.x & 31;
    if (warp >= MROWS * HH) return;
    size_t base = (size_t)warp * DVv;

    float vals[8];
    float ss = 0.f;
#pragma unroll
    for (int r = 0; r < 8; r++) {
        vals[r] = o[base + lane + 32 * r];
        ss += vals[r] * vals[r];
    }
#pragma unroll
    for (int off = 16; off; off >>= 1) ss += __shfl_xor_sync(0xFFFFFFFFu, ss, off);
    float inv = rsqrtf(ss * (1.0f / 256.0f) + 1e-5f);

#pragma unroll
    for (int r = 0; r < 8; r++) {
        int ev = lane + 32 * r;
        float gv = g[base + ev];
        float sg = 1.f / (1.f + expf(-gv));
        o[base + ev] = vals[r] * inv * norm_w[ev] * gv * sg;
    }
}

// ---------------- launch ----------------
extern "C" void kernel_launch(void* const* d_in, const int* in_sizes, int n_in,
                              void* d_out, int out_size) {
    const float* x      = (const float*)d_in[0];
    const float* Wq     = (const float*)d_in[1];
    const float* Wk     = (const float*)d_in[2];
    const float* Wv     = (const float*)d_in[3];
    const float* Wg     = (const float*)d_in[4];
    const float* Wo     = (const float*)d_in[5];
    const float* norm_w = (const float*)d_in[6];
    float* out = (float*)d_out;

    float *q, *k, *v, *g, *o;
    cudaGetSymbolAddress((void**)&q, g_q);
    cudaGetSymbolAddress((void**)&k, g_k);
    cudaGetSymbolAddress((void**)&v, g_v);
    cudaGetSymbolAddress((void**)&g, g_g);
    cudaGetSymbolAddress((void**)&o, g_o);

    const int smem_bytes = RET_SMEM_FLOATS * sizeof(float);
    cudaFuncSetAttribute(retention_kernel,
                         cudaFuncAttributeMaxDynamicSharedMemorySize, smem_bytes);

    // projections
    sgemm128<<<dim3(DD / 128,      MROWS / 128), 256>>>(x, Wq, q, MROWS, HH * DKk, DD);
    sgemm128<<<dim3(DD / 128,      MROWS / 128), 256>>>(x, Wk, k, MROWS, HH * DKk, DD);
    sgemm128<<<dim3(2 * DD / 128,  MROWS / 128), 256>>>(x, Wv, v, MROWS, HH * DVv, DD);
    sgemm128<<<dim3(2 * DD / 128,  MROWS / 128), 256>>>(x, Wg, g, MROWS, HH * DVv, DD);

    // rope + scale
    {
        int total = BB * TT * HH * (DKk / 2);
        rope_kernel<<<(total + 255) / 256, 256>>>(q, k);
    }

    // chunked retention
    retention_kernel<<<dim3(DVv / 64, HH, BB), 256, smem_bytes>>>(q, k, v, o);

    // rmsnorm + gate
    {
        int warps = MROWS * HH;
        normgate_kernel<<<(warps * 32 + 255) / 256, 256>>>(o, g, norm_w);
    }

    // output projection
    sgemm128<<<dim3(DD / 128, MROWS / 128), 256>>>(o, Wo, out, MROWS, DD, HH * DVv);
}

// round 3
// speedup vs baseline: 1.8143x; 1.8143x over previous
#include <cuda_runtime.h>
#include <cuda_bf16.h>
#include <math.h>
#include <stdint.h>

// ---------------- problem constants ----------------
#define BB 4
#define TT 2048
#define DD 1024
#define HH 8
#define DKk 128
#define DVv 256
#define CC 64
#define NCHUNK (TT / CC)   // 32
#define MROWS (BB * TT)    // 8192

// ---------------- scratch (no runtime allocation allowed) ----------------
__device__ float g_q[MROWS * HH * DKk];
__device__ float g_k[MROWS * HH * DKk];
__device__ float g_v[MROWS * HH * DVv];
__device__ float g_g[MROWS * HH * DVv];
__device__ float g_o[MROWS * HH * DVv];

// bf16 split operands
__device__ __nv_bfloat16 g_xhi[MROWS * DD];
__device__ __nv_bfloat16 g_xlo[MROWS * DD];
__device__ __nv_bfloat16 g_ohi[MROWS * HH * DVv];
__device__ __nv_bfloat16 g_olo[MROWS * HH * DVv];
// transposed weights [N, K]
__device__ __nv_bfloat16 g_wq_hi[DD * DD],       g_wq_lo[DD * DD];
__device__ __nv_bfloat16 g_wk_hi[DD * DD],       g_wk_lo[DD * DD];
__device__ __nv_bfloat16 g_wv_hi[2 * DD * DD],   g_wv_lo[2 * DD * DD];
__device__ __nv_bfloat16 g_wg_hi[2 * DD * DD],   g_wg_lo[2 * DD * DD];
__device__ __nv_bfloat16 g_wo_hi[2 * DD * DD],   g_wo_lo[2 * DD * DD];

// ================= PTX helpers (plain sm_80+ ISA only) =================
__device__ __forceinline__ uint32_t smem_u32(const void* p) {
    uint32_t a;
    asm("{ .reg .u64 t; cvta.to.shared.u64 t, %1; cvt.u32.u64 %0, t; }" : "=r"(a) : "l"(p));
    return a;
}
#define CP_ASYNC16(dst, src) \
    asm volatile("cp.async.cg.shared.global [%0], [%1], 16;" :: "r"(dst), "l"(src))
#define CP_ASYNC_COMMIT() asm volatile("cp.async.commit_group;" ::: "memory")
#define CP_ASYNC_WAIT2() asm volatile("cp.async.wait_group 2;" ::: "memory")

__device__ __forceinline__ void ldsm4(uint32_t* r, uint32_t addr) {
    asm volatile("ldmatrix.sync.aligned.m8n8.x4.shared.b16 {%0,%1,%2,%3}, [%4];"
        : "=r"(r[0]), "=r"(r[1]), "=r"(r[2]), "=r"(r[3]) : "r"(addr));
}
__device__ __forceinline__ void mma16816(float* c, const uint32_t* a, const uint32_t* b) {
    asm volatile("mma.sync.aligned.m16n8k16.row.col.f32.bf16.bf16.f32 "
        "{%0,%1,%2,%3}, {%4,%5,%6,%7}, {%8,%9}, {%0,%1,%2,%3};"
        : "+f"(c[0]), "+f"(c[1]), "+f"(c[2]), "+f"(c[3])
        : "r"(a[0]), "r"(a[1]), "r"(a[2]), "r"(a[3]), "r"(b[0]), "r"(b[1]));
}

// ================= split-bf16 tensor-core GEMM =================
// C[M,N] fp32 = Ahi@Bhi^T + Ahi@Blo^T + Alo@Bhi^T
// A*: [M,K] bf16 row-major. B*: [N,K] bf16 row-major (pre-transposed weights).
// Block tile 128x128, K-chunk 32, 3-stage cp.async pipeline.
#define GSTAGES 3
#define GPAD 40                                   // smem row stride in bf16 (80B)
#define GMAT_BYTES (128 * GPAD * 2)               // 10240
#define GSTAGE_BYTES (4 * GMAT_BYTES)             // Ahi,Alo,Bhi,Blo = 40960
#define GEMM_SMEM_BYTES (GSTAGES * GSTAGE_BYTES)  // 122880

// load one 128x32 bf16 tile (row-major, ldk elements per row) into padded smem
__device__ __forceinline__ void load_tile32(uint32_t dst, const __nv_bfloat16* src,
                                            int row0, int k0, int ldk, int tid) {
    const char* gbase = (const char*)(src + (size_t)row0 * ldk + k0);
    const size_t rowb = (size_t)ldk * 2;
#pragma unroll
    for (int j = 0; j < 2; j++) {
        int e = tid + j * 256;          // 0..511
        int r = e >> 2, c16 = e & 3;    // 128 rows x 4 chunks of 16B
        CP_ASYNC16(dst + r * (GPAD * 2) + c16 * 16, gbase + (size_t)r * rowb + c16 * 16);
    }
}

__global__ __launch_bounds__(256) void gemm_split_mma(
    const __nv_bfloat16* __restrict__ Ahi, const __nv_bfloat16* __restrict__ Alo,
    const __nv_bfloat16* __restrict__ Bhi, const __nv_bfloat16* __restrict__ Blo,
    float* __restrict__ C, int M, int N, int K) {
    extern __shared__ char smem[];
    const uint32_t sb = smem_u32(smem);
    const int tid = threadIdx.x, lane = tid & 31, wid = tid >> 5;
    const int wm = wid & 3, wn = wid >> 2;            // 4 x 2 warp grid
    const int m0 = blockIdx.y * 128, n0 = blockIdx.x * 128;
    const int nchunk = K >> 5;

    // ldmatrix lane addressing (byte offsets within a tile, before k-step col add)
    // A: row = mbase + (l%8) + 8*((l/8)%2), col8 = (l/16)
    const int a_row = (lane & 7) + 8 * ((lane >> 3) & 1);
    const int a_c8  = lane >> 4;
    // B: row = nbase + (l%8) + 8*(l/16),  col8 = ((l/8)%2)
    const int b_row = (lane & 7) + 8 * (lane >> 4);
    const int b_c8  = (lane >> 3) & 1;

    float acc[2][8][4];
#pragma unroll
    for (int i = 0; i < 2; i++)
#pragma unroll
        for (int j = 0; j < 8; j++)
#pragma unroll
            for (int r = 0; r < 4; r++) acc[i][j][r] = 0.f;

    // prologue
#pragma unroll
    for (int s = 0; s < GSTAGES; s++) {
        uint32_t st = sb + s * GSTAGE_BYTES;
        int k0 = s * 32;
        load_tile32(st,                 Ahi, m0, k0, K, tid);
        load_tile32(st + GMAT_BYTES,    Alo, m0, k0, K, tid);
        load_tile32(st + 2 * GMAT_BYTES, Bhi, n0, k0, K, tid);
        load_tile32(st + 3 * GMAT_BYTES, Blo, n0, k0, K, tid);
        CP_ASYNC_COMMIT();
    }

    for (int c = 0; c < nchunk; c++) {
        uint32_t st = sb + (c % GSTAGES) * GSTAGE_BYTES;
        CP_ASYNC_WAIT2();
        __syncthreads();

        const uint32_t sAhi = st + (wm * 32 + a_row) * (GPAD * 2) + a_c8 * 16;
        const uint32_t sAlo = sAhi + GMAT_BYTES;
        const uint32_t sBhi = st + 2 * GMAT_BYTES + (wn * 64 + b_row) * (GPAD * 2) + b_c8 * 16;
        const uint32_t sBlo = sBhi + GMAT_BYTES;

#pragma unroll
        for (int ks = 0; ks < 2; ks++) {     // k = 0, 16 within chunk
            const uint32_t kb = ks * 32;     // bytes
            uint32_t ah[2][4], al[2][4];
#pragma unroll
            for (int mt = 0; mt < 2; mt++) {
                ldsm4(ah[mt], sAhi + mt * 16 * (GPAD * 2) + kb);
                ldsm4(al[mt], sAlo + mt * 16 * (GPAD * 2) + kb);
            }
            uint32_t bh[4][4], bl[4][4];
#pragma unroll
            for (int np = 0; np < 4; np++) {
                ldsm4(bh[np], sBhi + np * 16 * (GPAD * 2) + kb);
                ldsm4(bl[np], sBlo + np * 16 * (GPAD * 2) + kb);
            }
#pragma unroll
            for (int mt = 0; mt < 2; mt++)
#pragma unroll
                for (int nt = 0; nt < 8; nt++) {
                    const uint32_t* bfh = &bh[nt >> 1][(nt & 1) * 2];
                    const uint32_t* bfl = &bl[nt >> 1][(nt & 1) * 2];
                    mma16816(acc[mt][nt], ah[mt], bfh);   // hi*hi
                    mma16816(acc[mt][nt], ah[mt], bfl);   // hi*lo
                    mma16816(acc[mt][nt], al[mt], bfh);   // lo*hi
                }
        }
        __syncthreads();

        if (c + GSTAGES < nchunk) {
            int k0 = (c + GSTAGES) * 32;
            load_tile32(st,                 Ahi, m0, k0, K, tid);
            load_tile32(st + GMAT_BYTES,    Alo, m0, k0, K, tid);
            load_tile32(st + 2 * GMAT_BYTES, Bhi, n0, k0, K, tid);
            load_tile32(st + 3 * GMAT_BYTES, Blo, n0, k0, K, tid);
        }
        CP_ASYNC_COMMIT();
    }

    // epilogue: mma C-frag layout
    const int crow = lane >> 2, ccol = (lane & 3) * 2;
#pragma unroll
    for (int mt = 0; mt < 2; mt++) {
        int rbase = m0 + wm * 32 + mt * 16 + crow;
#pragma unroll
        for (int nt = 0; nt < 8; nt++) {
            int cbase = n0 + wn * 64 + nt * 8 + ccol;
            float* d0 = C + (size_t)rbase * N + cbase;
            float* d1 = C + (size_t)(rbase + 8) * N + cbase;
            *(float2*)d0 = make_float2(acc[mt][nt][0], acc[mt][nt][1]);
            *(float2*)d1 = make_float2(acc[mt][nt][2], acc[mt][nt][3]);
        }
    }
}

// ================= split / transpose-split =================
__global__ __launch_bounds__(256) void split_kernel(const float* __restrict__ in,
                                                    __nv_bfloat16* __restrict__ hi,
                                                    __nv_bfloat16* __restrict__ lo, int n) {
    int i = blockIdx.x * blockDim.x + threadIdx.x;
    if (i >= n) return;
    float v = in[i];
    __nv_bfloat16 h = __float2bfloat16(v);
    hi[i] = h;
    lo[i] = __float2bfloat16(v - __bfloat162float(h));
}

// W: [K, N] fp32 -> Thi/Tlo: [N, K] bf16
__global__ __launch_bounds__(256) void tsplit_kernel(const float* __restrict__ W,
                                                     __nv_bfloat16* __restrict__ Thi,
                                                     __nv_bfloat16* __restrict__ Tlo,
                                                     int K, int N) {
    __shared__ float t[32][33];
    int n0 = blockIdx.x * 32, k0 = blockIdx.y * 32;
    int tx = threadIdx.x & 31, ty = threadIdx.x >> 5;  // 32x8
#pragma unroll
    for (int i = ty; i < 32; i += 8)
        t[i][tx] = W[(size_t)(k0 + i) * N + n0 + tx];
    __syncthreads();
#pragma unroll
    for (int i = ty; i < 32; i += 8) {
        float v = t[tx][i];  // k=k0+tx, n=n0+i
        __nv_bfloat16 h = __float2bfloat16(v);
        size_t oidx = (size_t)(n0 + i) * K + k0 + tx;
        Thi[oidx] = h;
        Tlo[oidx] = __float2bfloat16(v - __bfloat162float(h));
    }
}

// ---------------- RoPE (in place on q and k), q also scaled by DK^-1/2 ----------------
__global__ void rope_kernel(float* __restrict__ q, float* __restrict__ k) {
    int idx = blockIdx.x * blockDim.x + threadIdx.x;
    const int total = BB * TT * HH * (DKk / 2);
    if (idx >= total) return;
    int i = idx & 63;
    int h = (idx >> 6) & (HH - 1);
    int t = (idx >> 9) & (TT - 1);
    int b = idx >> 20;

    float inv = powf(10000.f, -(float)i * (1.0f / 64.0f));
    float f = (float)t * inv;
    float s, c;
    sincosf(f, &s, &c);

    size_t base = ((((size_t)b * TT + t) * HH + h) << 7);
    const float sc = 0.08838834764831845f;
    float q1 = q[base + i], q2 = q[base + 64 + i];
    q[base + i]      = (q1 * c - q2 * s) * sc;
    q[base + 64 + i] = (q2 * c + q1 * s) * sc;
    float k1 = k[base + i], k2 = k[base + 64 + i];
    k[base + i]      = k1 * c - k2 * s;
    k[base + 64 + i] = k2 * c + k1 * s;
}

// ---------------- chunked retention ----------------
#define RET_SMEM_FLOATS (128 * 65 + 2 * 64 * 129 + 2 * 64 * 65 + 3 * 64)

__global__ __launch_bounds__(256) void retention_kernel(const float* __restrict__ q,
                                                        const float* __restrict__ k,
                                                        const float* __restrict__ v,
                                                        float* __restrict__ o) {
    const int sl = blockIdx.x;
    const int h  = blockIdx.y;
    const int b  = blockIdx.z;
    const int tid = threadIdx.x;

    extern __shared__ float sm[];
    float* S    = sm;
    float* qs   = S + 128 * 65;
    float* ks   = qs + 64 * 129;
    float* vs   = ks + 64 * 129;
    float* at   = vs + 64 * 65;
    float* gpow = at + 64 * 65;
    float* decq = gpow + 64;
    float* deck = decq + 64;

    const float gamma = 1.0f - exp2f(-5.0f - (float)h);
    if (tid < 64) {
        gpow[tid] = powf(gamma, (float)tid);
        decq[tid] = powf(gamma, (float)(tid + 1));
        deck[tid] = powf(gamma, (float)(63 - tid));
    }
    const float gC = powf(gamma, 64.0f);

    for (int e = tid; e < 128 * 65; e += 256) S[e] = 0.f;
    __syncthreads();

    const int ti = tid >> 4;
    const int te = tid & 15;

    for (int n = 0; n < NCHUNK; n++) {
        const int t0 = n * CC;
        for (int e = tid; e < 64 * 128; e += 256) {
            int i = e >> 7, dk = e & 127;
            size_t gi = ((((size_t)b * TT + t0 + i) * HH + h) << 7) + dk;
            qs[i * 129 + dk] = q[gi];
            ks[i * 129 + dk] = k[gi];
        }
        for (int e = tid; e < 64 * 64; e += 256) {
            int i = e >> 6, ev = e & 63;
            size_t gi = (((size_t)b * TT + t0 + i) * HH + h) * DVv + sl * 64 + ev;
            vs[i * 65 + ev] = v[gi];
        }
        __syncthreads();

        {
            float acc[4][4];
#pragma unroll
            for (int a = 0; a < 4; a++)
#pragma unroll
                for (int bq = 0; bq < 4; bq++) acc[a][bq] = 0.f;
            for (int dk = 0; dk < 128; dk++) {
                float ra[4], rb[4];
#pragma unroll
                for (int ii = 0; ii < 4; ii++) ra[ii] = qs[(ti * 4 + ii) * 129 + dk];
#pragma unroll
                for (int jj = 0; jj < 4; jj++) rb[jj] = ks[(te * 4 + jj) * 129 + dk];
#pragma unroll
                for (int ii = 0; ii < 4; ii++)
#pragma unroll
                    for (int jj = 0; jj < 4; jj++) acc[ii][jj] += ra[ii] * rb[jj];
            }
#pragma unroll
            for (int ii = 0; ii < 4; ii++)
#pragma unroll
                for (int jj = 0; jj < 4; jj++) {
                    int i = ti * 4 + ii, j = te * 4 + jj;
                    at[i * 65 + j] = (i >= j) ? acc[ii][jj] * gpow[i - j] : 0.f;
                }
        }
        __syncthreads();

        {
            float aI[4][4], aS[4][4];
#pragma unroll
            for (int a = 0; a < 4; a++)
#pragma unroll
                for (int bq = 0; bq < 4; bq++) { aI[a][bq] = 0.f; aS[a][bq] = 0.f; }
            for (int j = 0; j < 64; j++) {
                float ra[4], rb[4];
#pragma unroll
                for (int ii = 0; ii < 4; ii++) ra[ii] = at[(ti * 4 + ii) * 65 + j];
#pragma unroll
                for (int ee = 0; ee < 4; ee++) rb[ee] = vs[j * 65 + te * 4 + ee];
#pragma unroll
                for (int ii = 0; ii < 4; ii++)
#pragma unroll
                    for (int ee = 0; ee < 4; ee++) aI[ii][ee] += ra[ii] * rb[ee];
            }
            for (int dk = 0; dk < 128; dk++) {
                float ra[4], rb[4];
#pragma unroll
                for (int ii = 0; ii < 4; ii++) ra[ii] = qs[(ti * 4 + ii) * 129 + dk];
#pragma unroll
                for (int ee = 0; ee < 4; ee++) rb[ee] = S[dk * 65 + te * 4 + ee];
#pragma unroll
                for (int ii = 0; ii < 4; ii++)
#pragma unroll
                    for (int ee = 0; ee < 4; ee++) aS[ii][ee] += ra[ii] * rb[ee];
            }
#pragma unroll
            for (int ii = 0; ii < 4; ii++) {
                int i = ti * 4 + ii;
                float dq = decq[i];
                size_t base = (((size_t)b * TT + t0 + i) * HH + h) * DVv + sl * 64 + te * 4;
#pragma unroll
                for (int ee = 0; ee < 4; ee++)
                    o[base + ee] = aI[ii][ee] + dq * aS[ii][ee];
            }
        }
        __syncthreads();

        {
            float acc[8][4];
#pragma unroll
            for (int a = 0; a < 8; a++)
#pragma unroll
                for (int bq = 0; bq < 4; bq++) acc[a][bq] = 0.f;
            for (int j = 0; j < 64; j++) {
                float dkj = deck[j];
                float ra[8], rb[4];
#pragma unroll
                for (int dd = 0; dd < 8; dd++) ra[dd] = ks[j * 129 + ti * 8 + dd] * dkj;
#pragma unroll
                for (int ee = 0; ee < 4; ee++) rb[ee] = vs[j * 65 + te * 4 + ee];
#pragma unroll
                for (int dd = 0; dd < 8; dd++)
#pragma unroll
                    for (int ee = 0; ee < 4; ee++) acc[dd][ee] += ra[dd] * rb[ee];
            }
#pragma unroll
            for (int dd = 0; dd < 8; dd++)
#pragma unroll
                for (int ee = 0; ee < 4; ee++) {
                    int dk = ti * 8 + dd, ev = te * 4 + ee;
                    S[dk * 65 + ev] = gC * S[dk * 65 + ev] + acc[dd][ee];
                }
        }
        __syncthreads();
    }
}

// ---------------- RMSNorm + swish gate (in place on o) ----------------
__global__ __launch_bounds__(256) void normgate_kernel(float* __restrict__ o,
                                                       const float* __restrict__ g,
                                                       const float* __restrict__ norm_w) {
    int warp = (blockIdx.x * blockDim.x + threadIdx.x) >> 5;
    int lane = threadIdx.x & 31;
    if (warp >= MROWS * HH) return;
    size_t base = (size_t)warp * DVv;

    float vals[8];
    float ss = 0.f;
#pragma unroll
    for (int r = 0; r < 8; r++) {
        vals[r] = o[base + lane + 32 * r];
        ss += vals[r] * vals[r];
    }
#pragma unroll
    for (int off = 16; off; off >>= 1) ss += __shfl_xor_sync(0xFFFFFFFFu, ss, off);
    float inv = rsqrtf(ss * (1.0f / 256.0f) + 1e-5f);

#pragma unroll
    for (int r = 0; r < 8; r++) {
        int ev = lane + 32 * r;
        float gv = g[base + ev];
        float sg = 1.f / (1.f + expf(-gv));
        o[base + ev] = vals[r] * inv * norm_w[ev] * gv * sg;
    }
}

// ---------------- launch ----------------
static void launch_gemm(const __nv_bfloat16* Ahi, const __nv_bfloat16* Alo,
                        const __nv_bfloat16* Bhi, const __nv_bfloat16* Blo,
                        float* C, int M, int N, int K) {
    gemm_split_mma<<<dim3(N / 128, M / 128), 256, GEMM_SMEM_BYTES>>>(Ahi, Alo, Bhi, Blo, C, M, N, K);
}

extern "C" void kernel_launch(void* const* d_in, const int* in_sizes, int n_in,
                              void* d_out, int out_size) {
    const float* x      = (const float*)d_in[0];
    const float* Wq     = (const float*)d_in[1];
    const float* Wk     = (const float*)d_in[2];
    const float* Wv     = (const float*)d_in[3];
    const float* Wg     = (const float*)d_in[4];
    const float* Wo     = (const float*)d_in[5];
    const float* norm_w = (const float*)d_in[6];
    float* out = (float*)d_out;

    float *q, *k, *v, *g, *o;
    cudaGetSymbolAddress((void**)&q, g_q);
    cudaGetSymbolAddress((void**)&k, g_k);
    cudaGetSymbolAddress((void**)&v, g_v);
    cudaGetSymbolAddress((void**)&g, g_g);
    cudaGetSymbolAddress((void**)&o, g_o);
    __nv_bfloat16 *xhi, *xlo, *ohi, *olo;
    __nv_bfloat16 *wqh, *wql, *wkh, *wkl, *wvh, *wvl, *wgh, *wgl, *woh, *wol;
    cudaGetSymbolAddress((void**)&xhi, g_xhi);
    cudaGetSymbolAddress((void**)&xlo, g_xlo);
    cudaGetSymbolAddress((void**)&ohi, g_ohi);
    cudaGetSymbolAddress((void**)&olo, g_olo);
    cudaGetSymbolAddress((void**)&wqh, g_wq_hi); cudaGetSymbolAddress((void**)&wql, g_wq_lo);
    cudaGetSymbolAddress((void**)&wkh, g_wk_hi); cudaGetSymbolAddress((void**)&wkl, g_wk_lo);
    cudaGetSymbolAddress((void**)&wvh, g_wv_hi); cudaGetSymbolAddress((void**)&wvl, g_wv_lo);
    cudaGetSymbolAddress((void**)&wgh, g_wg_hi); cudaGetSymbolAddress((void**)&wgl, g_wg_lo);
    cudaGetSymbolAddress((void**)&woh, g_wo_hi); cudaGetSymbolAddress((void**)&wol, g_wo_lo);

    const int ret_smem = RET_SMEM_FLOATS * sizeof(float);
    cudaFuncSetAttribute(retention_kernel, cudaFuncAttributeMaxDynamicSharedMemorySize, ret_smem);
    cudaFuncSetAttribute(gemm_split_mma, cudaFuncAttributeMaxDynamicSharedMemorySize, GEMM_SMEM_BYTES);

    // split inputs + transpose-split weights
    {
        int n = MROWS * DD;
        split_kernel<<<(n + 255) / 256, 256>>>(x, xhi, xlo, n);
    }
    tsplit_kernel<<<dim3(DD / 32, DD / 32), 256>>>(Wq, wqh, wql, DD, DD);
    tsplit_kernel<<<dim3(DD / 32, DD / 32), 256>>>(Wk, wkh, wkl, DD, DD);
    tsplit_kernel<<<dim3(2 * DD / 32, DD / 32), 256>>>(Wv, wvh, wvl, DD, 2 * DD);
    tsplit_kernel<<<dim3(2 * DD / 32, DD / 32), 256>>>(Wg, wgh, wgl, DD, 2 * DD);
    tsplit_kernel<<<dim3(DD / 32, 2 * DD / 32), 256>>>(Wo, woh, wol, 2 * DD, DD);

    // projections on tensor cores
    launch_gemm(xhi, xlo, wqh, wql, q, MROWS, DD, DD);
    launch_gemm(xhi, xlo, wkh, wkl, k, MROWS, DD, DD);
    launch_gemm(xhi, xlo, wvh, wvl, v, MROWS, 2 * DD, DD);
    launch_gemm(xhi, xlo, wgh, wgl, g, MROWS, 2 * DD, DD);

    // rope + scale
    {
        int total = BB * TT * HH * (DKk / 2);
        rope_kernel<<<(total + 255) / 256, 256>>>(q, k);
    }

    // chunked retention
    retention_kernel<<<dim3(DVv / 64, HH, BB), 256, ret_smem>>>(q, k, v, o);

    // rmsnorm + gate
    {
        int warps = MROWS * HH;
        normgate_kernel<<<(warps * 32 + 255) / 256, 256>>>(o, g, norm_w);
    }

    // split o, then output projection on tensor cores
    {
        int n = MROWS * HH * DVv;
        split_kernel<<<(n + 255) / 256, 256>>>(o, ohi, olo, n);
    }
    launch_gemm(ohi, olo, woh, wol, out, MROWS, DD, 2 * DD);
}

// round 4
// speedup vs baseline: 2.2087x; 1.2174x over previous
#include <cuda_runtime.h>
#include <cuda_bf16.h>
#include <math.h>
#include <stdint.h>

// ---------------- problem constants ----------------
#define BB 4
#define TT 2048
#define DD 1024
#define HH 8
#define DKk 128
#define DVv 256
#define CC 64
#define NCHUNK (TT / CC)   // 32
#define MROWS (BB * TT)    // 8192

// ---------------- scratch (no runtime allocation allowed) ----------------
__device__ float g_q[MROWS * HH * DKk];
__device__ float g_k[MROWS * HH * DKk];
__device__ float g_v[MROWS * HH * DVv];
__device__ float g_g[MROWS * HH * DVv];
__device__ float g_o[MROWS * HH * DVv];

// bf16 split operands
__device__ __nv_bfloat16 g_xhi[MROWS * DD];
__device__ __nv_bfloat16 g_xlo[MROWS * DD];
__device__ __nv_bfloat16 g_ohi[MROWS * HH * DVv];
__device__ __nv_bfloat16 g_olo[MROWS * HH * DVv];
// transposed weights [N, K]
__device__ __nv_bfloat16 g_wq_hi[DD * DD],       g_wq_lo[DD * DD];
__device__ __nv_bfloat16 g_wk_hi[DD * DD],       g_wk_lo[DD * DD];
__device__ __nv_bfloat16 g_wv_hi[2 * DD * DD],   g_wv_lo[2 * DD * DD];
__device__ __nv_bfloat16 g_wg_hi[2 * DD * DD],   g_wg_lo[2 * DD * DD];
__device__ __nv_bfloat16 g_wo_hi[2 * DD * DD],   g_wo_lo[2 * DD * DD];

// ================= PTX helpers (plain sm_80+ ISA only) =================
__device__ __forceinline__ uint32_t smem_u32(const void* p) {
    uint32_t a;
    asm("{ .reg .u64 t; cvta.to.shared.u64 t, %1; cvt.u32.u64 %0, t; }" : "=r"(a) : "l"(p));
    return a;
}
#define CP_ASYNC16(dst, src) \
    asm volatile("cp.async.cg.shared.global [%0], [%1], 16;" :: "r"(dst), "l"(src))
#define CP_ASYNC_COMMIT() asm volatile("cp.async.commit_group;" ::: "memory")
#define CP_ASYNC_WAIT2() asm volatile("cp.async.wait_group 2;" ::: "memory")

__device__ __forceinline__ void ldsm4(uint32_t* r, uint32_t addr) {
    asm volatile("ldmatrix.sync.aligned.m8n8.x4.shared.b16 {%0,%1,%2,%3}, [%4];"
        : "=r"(r[0]), "=r"(r[1]), "=r"(r[2]), "=r"(r[3]) : "r"(addr));
}
__device__ __forceinline__ void mma16816(float* c, const uint32_t* a, const uint32_t* b) {
    asm volatile("mma.sync.aligned.m16n8k16.row.col.f32.bf16.bf16.f32 "
        "{%0,%1,%2,%3}, {%4,%5,%6,%7}, {%8,%9}, {%0,%1,%2,%3};"
        : "+f"(c[0]), "+f"(c[1]), "+f"(c[2]), "+f"(c[3])
        : "r"(a[0]), "r"(a[1]), "r"(a[2]), "r"(a[3]), "r"(b[0]), "r"(b[1]));
}

// ================= split-bf16 tensor-core GEMM =================
// C[M,N] fp32 = Ahi@Bhi^T + Ahi@Blo^T + Alo@Bhi^T
// A*: [M,K] bf16 row-major. B*: [N,K] bf16 row-major (pre-transposed weights).
// Block tile 128x128, K-chunk 32, 3-stage cp.async pipeline.
// SMEM tiles: 128 rows x 64B, XOR swizzle c' = c16 ^ ((row>>1)&3)  (conflict-free
// for both cp.async 16B stores and ldmatrix 8-row phases).
#define GSTAGES 3
#define GMAT_BYTES (128 * 64)                     // 8192
#define GSTAGE_BYTES (4 * GMAT_BYTES)             // Ahi,Alo,Bhi,Blo = 32768
#define GEMM_SMEM_BYTES (GSTAGES * GSTAGE_BYTES)  // 98304 -> 2 blocks/SM

__device__ __forceinline__ uint32_t swz(int row, int c16) {
    return (uint32_t)(row * 64 + ((c16 ^ ((row >> 1) & 3)) << 4));
}

// load one 128x32 bf16 tile (row-major, ldk elements per row) into swizzled smem
__device__ __forceinline__ void load_tile32(uint32_t dst, const __nv_bfloat16* src,
                                            int row0, int k0, int ldk, int tid) {
    const char* gbase = (const char*)(src + (size_t)row0 * ldk + k0);
    const size_t rowb = (size_t)ldk * 2;
#pragma unroll
    for (int j = 0; j < 2; j++) {
        int e = tid + j * 256;          // 0..511
        int r = e >> 2, c16 = e & 3;    // 128 rows x 4 chunks of 16B
        CP_ASYNC16(dst + swz(r, c16), gbase + (size_t)r * rowb + c16 * 16);
    }
}

__global__ __launch_bounds__(256, 2) void gemm_split_mma(
    const __nv_bfloat16* __restrict__ Ahi, const __nv_bfloat16* __restrict__ Alo,
    const __nv_bfloat16* __restrict__ Bhi, const __nv_bfloat16* __restrict__ Blo,
    float* __restrict__ C, int M, int N, int K) {
    extern __shared__ char smem[];
    const uint32_t sb = smem_u32(smem);
    const int tid = threadIdx.x, lane = tid & 31, wid = tid >> 5;
    const int wm = wid & 3, wn = wid >> 2;            // 4 x 2 warp grid
    const int m0 = blockIdx.y * 128, n0 = blockIdx.x * 128;
    const int nchunk = K >> 5;

    // ldmatrix lane addressing
    const int a_row = (lane & 7) + 8 * ((lane >> 3) & 1);
    const int a_c8  = lane >> 4;            // 0..1 (16B chunk within 32B k-step)
    const int b_row = (lane & 7) + 8 * (lane >> 4);
    const int b_c8  = (lane >> 3) & 1;

    const int arow = wm * 32 + a_row;       // +mt*16 / +8 phases don't change sel
    const int selA = (arow >> 1) & 3;
    const int brow = wn * 64 + b_row;
    const int selB = (brow >> 1) & 3;

    float acc[2][8][4];
#pragma unroll
    for (int i = 0; i < 2; i++)
#pragma unroll
        for (int j = 0; j < 8; j++)
#pragma unroll
            for (int r = 0; r < 4; r++) acc[i][j][r] = 0.f;

    // prologue
#pragma unroll
    for (int s = 0; s < GSTAGES; s++) {
        uint32_t st = sb + s * GSTAGE_BYTES;
        int k0 = s * 32;
        load_tile32(st,                  Ahi, m0, k0, K, tid);
        load_tile32(st + GMAT_BYTES,     Alo, m0, k0, K, tid);
        load_tile32(st + 2 * GMAT_BYTES, Bhi, n0, k0, K, tid);
        load_tile32(st + 3 * GMAT_BYTES, Blo, n0, k0, K, tid);
        CP_ASYNC_COMMIT();
    }

    for (int c = 0; c < nchunk; c++) {
        uint32_t st = sb + (c % GSTAGES) * GSTAGE_BYTES;
        CP_ASYNC_WAIT2();
        __syncthreads();

#pragma unroll
        for (int ks = 0; ks < 2; ks++) {     // k = 0, 16 within chunk
            const int ks2 = ks * 2;
            const uint32_t ca = (uint32_t)(((ks2 + a_c8) ^ selA) << 4);
            const uint32_t cb = (uint32_t)(((ks2 + b_c8) ^ selB) << 4);

            uint32_t ah[2][4], al[2][4];
#pragma unroll
            for (int mt = 0; mt < 2; mt++) {
                uint32_t ra = st + (uint32_t)((arow + mt * 16) * 64) + ca;
                ldsm4(ah[mt], ra);
                ldsm4(al[mt], ra + GMAT_BYTES);
            }
#pragma unroll
            for (int np = 0; np < 4; np++) {
                uint32_t bh[4], bl[4];
                uint32_t rb = st + 2 * GMAT_BYTES + (uint32_t)((brow + np * 16) * 64) + cb;
                ldsm4(bh, rb);
                ldsm4(bl, rb + GMAT_BYTES);
#pragma unroll
                for (int mt = 0; mt < 2; mt++)
#pragma unroll
                    for (int hf = 0; hf < 2; hf++) {
                        float* a4 = acc[mt][np * 2 + hf];
                        mma16816(a4, ah[mt], &bh[hf * 2]);   // hi*hi
                        mma16816(a4, ah[mt], &bl[hf * 2]);   // hi*lo
                        mma16816(a4, al[mt], &bh[hf * 2]);   // lo*hi
                    }
            }
        }
        __syncthreads();

        if (c + GSTAGES < nchunk) {
            int k0 = (c + GSTAGES) * 32;
            load_tile32(st,                  Ahi, m0, k0, K, tid);
            load_tile32(st + GMAT_BYTES,     Alo, m0, k0, K, tid);
            load_tile32(st + 2 * GMAT_BYTES, Bhi, n0, k0, K, tid);
            load_tile32(st + 3 * GMAT_BYTES, Blo, n0, k0, K, tid);
        }
        CP_ASYNC_COMMIT();
    }

    // epilogue
    const int crow = lane >> 2, ccol = (lane & 3) * 2;
#pragma unroll
    for (int mt = 0; mt < 2; mt++) {
        int rbase = m0 + wm * 32 + mt * 16 + crow;
#pragma unroll
        for (int nt = 0; nt < 8; nt++) {
            int cbase = n0 + wn * 64 + nt * 8 + ccol;
            float* d0 = C + (size_t)rbase * N + cbase;
            float* d1 = C + (size_t)(rbase + 8) * N + cbase;
            *(float2*)d0 = make_float2(acc[mt][nt][0], acc[mt][nt][1]);
            *(float2*)d1 = make_float2(acc[mt][nt][2], acc[mt][nt][3]);
        }
    }
}

// ================= split / transpose-split =================
__global__ __launch_bounds__(256) void split_kernel(const float* __restrict__ in,
                                                    __nv_bfloat16* __restrict__ hi,
                                                    __nv_bfloat16* __restrict__ lo, int n) {
    int i = blockIdx.x * blockDim.x + threadIdx.x;
    if (i >= n) return;
    float v = in[i];
    __nv_bfloat16 h = __float2bfloat16(v);
    hi[i] = h;
    lo[i] = __float2bfloat16(v - __bfloat162float(h));
}

// W: [K, N] fp32 -> Thi/Tlo: [N, K] bf16
__global__ __launch_bounds__(256) void tsplit_kernel(const float* __restrict__ W,
                                                     __nv_bfloat16* __restrict__ Thi,
                                                     __nv_bfloat16* __restrict__ Tlo,
                                                     int K, int N) {
    __shared__ float t[32][33];
    int n0 = blockIdx.x * 32, k0 = blockIdx.y * 32;
    int tx = threadIdx.x & 31, ty = threadIdx.x >> 5;  // 32x8
#pragma unroll
    for (int i = ty; i < 32; i += 8)
        t[i][tx] = W[(size_t)(k0 + i) * N + n0 + tx];
    __syncthreads();
#pragma unroll
    for (int i = ty; i < 32; i += 8) {
        float v = t[tx][i];  // k=k0+tx, n=n0+i
        __nv_bfloat16 h = __float2bfloat16(v);
        size_t oidx = (size_t)(n0 + i) * K + k0 + tx;
        Thi[oidx] = h;
        Tlo[oidx] = __float2bfloat16(v - __bfloat162float(h));
    }
}

// ---------------- RoPE (in place on q and k), q also scaled by DK^-1/2 ----------------
__global__ void rope_kernel(float* __restrict__ q, float* __restrict__ k) {
    int idx = blockIdx.x * blockDim.x + threadIdx.x;
    const int total = BB * TT * HH * (DKk / 2);
    if (idx >= total) return;
    int i = idx & 63;
    int h = (idx >> 6) & (HH - 1);
    int t = (idx >> 9) & (TT - 1);
    int b = idx >> 20;

    float inv = powf(10000.f, -(float)i * (1.0f / 64.0f));
    float f = (float)t * inv;
    float s, c;
    sincosf(f, &s, &c);

    size_t base = ((((size_t)b * TT + t) * HH + h) << 7);
    const float sc = 0.08838834764831845f;
    float q1 = q[base + i], q2 = q[base + 64 + i];
    q[base + i]      = (q1 * c - q2 * s) * sc;
    q[base + 64 + i] = (q2 * c + q1 * s) * sc;
    float k1 = k[base + i], k2 = k[base + 64 + i];
    k[base + i]      = k1 * c - k2 * s;
    k[base + 64 + i] = k2 * c + k1 * s;
}

// ---------------- chunked retention ----------------
#define RET_SMEM_FLOATS (128 * 65 + 2 * 64 * 129 + 2 * 64 * 65 + 3 * 64)

__global__ __launch_bounds__(256) void retention_kernel(const float* __restrict__ q,
                                                        const float* __restrict__ k,
                                                        const float* __restrict__ v,
                                                        float* __restrict__ o) {
    const int sl = blockIdx.x;
    const int h  = blockIdx.y;
    const int b  = blockIdx.z;
    const int tid = threadIdx.x;

    extern __shared__ float sm[];
    float* S    = sm;
    float* qs   = S + 128 * 65;
    float* ks   = qs + 64 * 129;
    float* vs   = ks + 64 * 129;
    float* at   = vs + 64 * 65;
    float* gpow = at + 64 * 65;
    float* decq = gpow + 64;
    float* deck = decq + 64;

    const float gamma = 1.0f - exp2f(-5.0f - (float)h);
    if (tid < 64) {
        gpow[tid] = powf(gamma, (float)tid);
        decq[tid] = powf(gamma, (float)(tid + 1));
        deck[tid] = powf(gamma, (float)(63 - tid));
    }
    const float gC = powf(gamma, 64.0f);

    for (int e = tid; e < 128 * 65; e += 256) S[e] = 0.f;
    __syncthreads();

    const int ti = tid >> 4;
    const int te = tid & 15;

    for (int n = 0; n < NCHUNK; n++) {
        const int t0 = n * CC;
        for (int e = tid; e < 64 * 128; e += 256) {
            int i = e >> 7, dk = e & 127;
            size_t gi = ((((size_t)b * TT + t0 + i) * HH + h) << 7) + dk;
            qs[i * 129 + dk] = q[gi];
            ks[i * 129 + dk] = k[gi];
        }
        for (int e = tid; e < 64 * 64; e += 256) {
            int i = e >> 6, ev = e & 63;
            size_t gi = (((size_t)b * TT + t0 + i) * HH + h) * DVv + sl * 64 + ev;
            vs[i * 65 + ev] = v[gi];
        }
        __syncthreads();

        {
            float acc[4][4];
#pragma unroll
            for (int a = 0; a < 4; a++)
#pragma unroll
                for (int bq = 0; bq < 4; bq++) acc[a][bq] = 0.f;
            for (int dk = 0; dk < 128; dk++) {
                float ra[4], rb[4];
#pragma unroll
                for (int ii = 0; ii < 4; ii++) ra[ii] = qs[(ti * 4 + ii) * 129 + dk];
#pragma unroll
                for (int jj = 0; jj < 4; jj++) rb[jj] = ks[(te * 4 + jj) * 129 + dk];
#pragma unroll
                for (int ii = 0; ii < 4; ii++)
#pragma unroll
                    for (int jj = 0; jj < 4; jj++) acc[ii][jj] += ra[ii] * rb[jj];
            }
#pragma unroll
            for (int ii = 0; ii < 4; ii++)
#pragma unroll
                for (int jj = 0; jj < 4; jj++) {
                    int i = ti * 4 + ii, j = te * 4 + jj;
                    at[i * 65 + j] = (i >= j) ? acc[ii][jj] * gpow[i - j] : 0.f;
                }
        }
        __syncthreads();

        {
            float aI[4][4], aS[4][4];
#pragma unroll
            for (int a = 0; a < 4; a++)
#pragma unroll
                for (int bq = 0; bq < 4; bq++) { aI[a][bq] = 0.f; aS[a][bq] = 0.f; }
            for (int j = 0; j < 64; j++) {
                float ra[4], rb[4];
#pragma unroll
                for (int ii = 0; ii < 4; ii++) ra[ii] = at[(ti * 4 + ii) * 65 + j];
#pragma unroll
                for (int ee = 0; ee < 4; ee++) rb[ee] = vs[j * 65 + te * 4 + ee];
#pragma unroll
                for (int ii = 0; ii < 4; ii++)
#pragma unroll
                    for (int ee = 0; ee < 4; ee++) aI[ii][ee] += ra[ii] * rb[ee];
            }
            for (int dk = 0; dk < 128; dk++) {
                float ra[4], rb[4];
#pragma unroll
                for (int ii = 0; ii < 4; ii++) ra[ii] = qs[(ti * 4 + ii) * 129 + dk];
#pragma unroll
                for (int ee = 0; ee < 4; ee++) rb[ee] = S[dk * 65 + te * 4 + ee];
#pragma unroll
                for (int ii = 0; ii < 4; ii++)
#pragma unroll
                    for (int ee = 0; ee < 4; ee++) aS[ii][ee] += ra[ii] * rb[ee];
            }
#pragma unroll
            for (int ii = 0; ii < 4; ii++) {
                int i = ti * 4 + ii;
                float dq = decq[i];
                size_t base = (((size_t)b * TT + t0 + i) * HH + h) * DVv + sl * 64 + te * 4;
#pragma unroll
                for (int ee = 0; ee < 4; ee++)
                    o[base + ee] = aI[ii][ee] + dq * aS[ii][ee];
            }
        }
        __syncthreads();

        {
            float acc[8][4];
#pragma unroll
            for (int a = 0; a < 8; a++)
#pragma unroll
                for (int bq = 0; bq < 4; bq++) acc[a][bq] = 0.f;
            for (int j = 0; j < 64; j++) {
                float dkj = deck[j];
                float ra[8], rb[4];
#pragma unroll
                for (int dd = 0; dd < 8; dd++) ra[dd] = ks[j * 129 + ti * 8 + dd] * dkj;
#pragma unroll
                for (int ee = 0; ee < 4; ee++) rb[ee] = vs[j * 65 + te * 4 + ee];
#pragma unroll
                for (int dd = 0; dd < 8; dd++)
#pragma unroll
                    for (int ee = 0; ee < 4; ee++) acc[dd][ee] += ra[dd] * rb[ee];
            }
#pragma unroll
            for (int dd = 0; dd < 8; dd++)
#pragma unroll
                for (int ee = 0; ee < 4; ee++) {
                    int dk = ti * 8 + dd, ev = te * 4 + ee;
                    S[dk * 65 + ev] = gC * S[dk * 65 + ev] + acc[dd][ee];
                }
        }
        __syncthreads();
    }
}

// ---------------- RMSNorm + swish gate + bf16 split (fused) ----------------
__global__ __launch_bounds__(256) void normgate_split_kernel(const float* __restrict__ o,
                                                             const float* __restrict__ g,
                                                             const float* __restrict__ norm_w,
                                                             __nv_bfloat16* __restrict__ ohi,
                                                             __nv_bfloat16* __restrict__ olo) {
    int warp = (blockIdx.x * blockDim.x + threadIdx.x) >> 5;
    int lane = threadIdx.x & 31;
    if (warp >= MROWS * HH) return;
    size_t base = (size_t)warp * DVv;

    float vals[8];
    float ss = 0.f;
#pragma unroll
    for (int r = 0; r < 8; r++) {
        vals[r] = o[base + lane + 32 * r];
        ss += vals[r] * vals[r];
    }
#pragma unroll
    for (int off = 16; off; off >>= 1) ss += __shfl_xor_sync(0xFFFFFFFFu, ss, off);
    float inv = rsqrtf(ss * (1.0f / 256.0f) + 1e-5f);

#pragma unroll
    for (int r = 0; r < 8; r++) {
        int ev = lane + 32 * r;
        float gv = g[base + ev];
        float sg = 1.f / (1.f + expf(-gv));
        float res = vals[r] * inv * norm_w[ev] * gv * sg;
        __nv_bfloat16 h = __float2bfloat16(res);
        ohi[base + ev] = h;
        olo[base + ev] = __float2bfloat16(res - __bfloat162float(h));
    }
}

// ---------------- launch ----------------
static void launch_gemm(const __nv_bfloat16* Ahi, const __nv_bfloat16* Alo,
                        const __nv_bfloat16* Bhi, const __nv_bfloat16* Blo,
                        float* C, int M, int N, int K) {
    gemm_split_mma<<<dim3(N / 128, M / 128), 256, GEMM_SMEM_BYTES>>>(Ahi, Alo, Bhi, Blo, C, M, N, K);
}

extern "C" void kernel_launch(void* const* d_in, const int* in_sizes, int n_in,
                              void* d_out, int out_size) {
    const float* x      = (const float*)d_in[0];
    const float* Wq     = (const float*)d_in[1];
    const float* Wk     = (const float*)d_in[2];
    const float* Wv     = (const float*)d_in[3];
    const float* Wg     = (const float*)d_in[4];
    const float* Wo     = (const float*)d_in[5];
    const float* norm_w = (const float*)d_in[6];
    float* out = (float*)d_out;

    float *q, *k, *v, *g, *o;
    cudaGetSymbolAddress((void**)&q, g_q);
    cudaGetSymbolAddress((void**)&k, g_k);
    cudaGetSymbolAddress((void**)&v, g_v);
    cudaGetSymbolAddress((void**)&g, g_g);
    cudaGetSymbolAddress((void**)&o, g_o);
    __nv_bfloat16 *xhi, *xlo, *ohi, *olo;
    __nv_bfloat16 *wqh, *wql, *wkh, *wkl, *wvh, *wvl, *wgh, *wgl, *woh, *wol;
    cudaGetSymbolAddress((void**)&xhi, g_xhi);
    cudaGetSymbolAddress((void**)&xlo, g_xlo);
    cudaGetSymbolAddress((void**)&ohi, g_ohi);
    cudaGetSymbolAddress((void**)&olo, g_olo);
    cudaGetSymbolAddress((void**)&wqh, g_wq_hi); cudaGetSymbolAddress((void**)&wql, g_wq_lo);
    cudaGetSymbolAddress((void**)&wkh, g_wk_hi); cudaGetSymbolAddress((void**)&wkl, g_wk_lo);
    cudaGetSymbolAddress((void**)&wvh, g_wv_hi); cudaGetSymbolAddress((void**)&wvl, g_wv_lo);
    cudaGetSymbolAddress((void**)&wgh, g_wg_hi); cudaGetSymbolAddress((void**)&wgl, g_wg_lo);
    cudaGetSymbolAddress((void**)&woh, g_wo_hi); cudaGetSymbolAddress((void**)&wol, g_wo_lo);

    const int ret_smem = RET_SMEM_FLOATS * sizeof(float);
    cudaFuncSetAttribute(retention_kernel, cudaFuncAttributeMaxDynamicSharedMemorySize, ret_smem);
    cudaFuncSetAttribute(gemm_split_mma, cudaFuncAttributeMaxDynamicSharedMemorySize, GEMM_SMEM_BYTES);

    // split inputs + transpose-split weights
    {
        int n = MROWS * DD;
        split_kernel<<<(n + 255) / 256, 256>>>(x, xhi, xlo, n);
    }
    tsplit_kernel<<<dim3(DD / 32, DD / 32), 256>>>(Wq, wqh, wql, DD, DD);
    tsplit_kernel<<<dim3(DD / 32, DD / 32), 256>>>(Wk, wkh, wkl, DD, DD);
    tsplit_kernel<<<dim3(2 * DD / 32, DD / 32), 256>>>(Wv, wvh, wvl, DD, 2 * DD);
    tsplit_kernel<<<dim3(2 * DD / 32, DD / 32), 256>>>(Wg, wgh, wgl, DD, 2 * DD);
    tsplit_kernel<<<dim3(DD / 32, 2 * DD / 32), 256>>>(Wo, woh, wol, 2 * DD, DD);

    // projections on tensor cores
    launch_gemm(xhi, xlo, wqh, wql, q, MROWS, DD, DD);
    launch_gemm(xhi, xlo, wkh, wkl, k, MROWS, DD, DD);
    launch_gemm(xhi, xlo, wvh, wvl, v, MROWS, 2 * DD, DD);
    launch_gemm(xhi, xlo, wgh, wgl, g, MROWS, 2 * DD, DD);

    // rope + scale
    {
        int total = BB * TT * HH * (DKk / 2);
        rope_kernel<<<(total + 255) / 256, 256>>>(q, k);
    }

    // chunked retention
    retention_kernel<<<dim3(DVv / 64, HH, BB), 256, ret_smem>>>(q, k, v, o);

    // rmsnorm + gate + split (fused)
    {
        int warps = MROWS * HH;
        normgate_split_kernel<<<(warps * 32 + 255) / 256, 256>>>(o, g, norm_w, ohi, olo);
    }

    // output projection on tensor cores
    launch_gemm(ohi, olo, woh, wol, out, MROWS, DD, 2 * DD);
}

// round 5
// speedup vs baseline: 2.2646x; 1.0253x over previous
#include <cuda_runtime.h>
#include <cuda_bf16.h>
#include <math.h>
#include <stdint.h>

// ---------------- problem constants ----------------
#define BB 4
#define TT 2048
#define DD 1024
#define HH 8
#define DKk 128
#define DVv 256
#define CC 64
#define NCHUNK (TT / CC)   // 32
#define MROWS (BB * TT)    // 8192

// ---------------- scratch (no runtime allocation allowed) ----------------
__device__ float g_q[MROWS * HH * DKk];
__device__ float g_k[MROWS * HH * DKk];
__device__ float g_v[MROWS * HH * DVv];
__device__ float g_g[MROWS * HH * DVv];
__device__ float g_o[MROWS * HH * DVv];

// bf16 split operands
__device__ __nv_bfloat16 g_xhi[MROWS * DD];
__device__ __nv_bfloat16 g_xlo[MROWS * DD];
__device__ __nv_bfloat16 g_ohi[MROWS * HH * DVv];
__device__ __nv_bfloat16 g_olo[MROWS * HH * DVv];
// transposed weights [N, K]
__device__ __nv_bfloat16 g_wq_hi[DD * DD],       g_wq_lo[DD * DD];
__device__ __nv_bfloat16 g_wk_hi[DD * DD],       g_wk_lo[DD * DD];
__device__ __nv_bfloat16 g_wv_hi[2 * DD * DD],   g_wv_lo[2 * DD * DD];
__device__ __nv_bfloat16 g_wg_hi[2 * DD * DD],   g_wg_lo[2 * DD * DD];
__device__ __nv_bfloat16 g_wo_hi[2 * DD * DD],   g_wo_lo[2 * DD * DD];

// ================= PTX helpers (plain sm_80+ ISA only) =================
__device__ __forceinline__ uint32_t smem_u32(const void* p) {
    uint32_t a;
    asm("{ .reg .u64 t; cvta.to.shared.u64 t, %1; cvt.u32.u64 %0, t; }" : "=r"(a) : "l"(p));
    return a;
}
#define CP_ASYNC16(dst, src) \
    asm volatile("cp.async.cg.shared.global [%0], [%1], 16;" :: "r"(dst), "l"(src))
#define CP_ASYNC_COMMIT() asm volatile("cp.async.commit_group;" ::: "memory")
#define CP_ASYNC_WAIT2() asm volatile("cp.async.wait_group 2;" ::: "memory")

__device__ __forceinline__ void ldsm4(uint32_t* r, uint32_t addr) {
    asm volatile("ldmatrix.sync.aligned.m8n8.x4.shared.b16 {%0,%1,%2,%3}, [%4];"
        : "=r"(r[0]), "=r"(r[1]), "=r"(r[2]), "=r"(r[3]) : "r"(addr));
}
__device__ __forceinline__ void mma16816(float* c, const uint32_t* a, const uint32_t* b) {
    asm volatile("mma.sync.aligned.m16n8k16.row.col.f32.bf16.bf16.f32 "
        "{%0,%1,%2,%3}, {%4,%5,%6,%7}, {%8,%9}, {%0,%1,%2,%3};"
        : "+f"(c[0]), "+f"(c[1]), "+f"(c[2]), "+f"(c[3])
        : "r"(a[0]), "r"(a[1]), "r"(a[2]), "r"(a[3]), "r"(b[0]), "r"(b[1]));
}

// ================= split-bf16 tensor-core GEMM =================
// C[M,N] fp32 = Ahi@Bhi^T + Ahi@Blo^T + Alo@Bhi^T
// A*: [M,K] bf16 row-major. B*: [N,K] bf16 row-major (pre-transposed weights).
// Block tile 128x128, K-chunk 32, 3-stage cp.async pipeline.
// 128 threads (4 warps, 2x2 grid, 64x64 warp tile) -> minimal ldmatrix traffic.
// SMEM tiles: 128 rows x 64B, XOR swizzle c' = c16 ^ ((row>>1)&3).
#define GSTAGES 3
#define GMAT_BYTES (128 * 64)                     // 8192
#define GSTAGE_BYTES (4 * GMAT_BYTES)             // Ahi,Alo,Bhi,Blo = 32768
#define GEMM_SMEM_BYTES (GSTAGES * GSTAGE_BYTES)  // 98304 -> 2 blocks/SM

__device__ __forceinline__ uint32_t swz(int row, int c16) {
    return (uint32_t)(row * 64 + ((c16 ^ ((row >> 1) & 3)) << 4));
}

// load one 128x32 bf16 tile (row-major, ldk elements per row) into swizzled smem
// 512 16B-chunks over 128 threads (4 each)
__device__ __forceinline__ void load_tile32(uint32_t dst, const __nv_bfloat16* src,
                                            int row0, int k0, int ldk, int tid) {
    const char* gbase = (const char*)(src + (size_t)row0 * ldk + k0);
    const size_t rowb = (size_t)ldk * 2;
#pragma unroll
    for (int j = 0; j < 4; j++) {
        int e = tid + j * 128;          // 0..511
        int r = e >> 2, c16 = e & 3;    // 128 rows x 4 chunks of 16B
        CP_ASYNC16(dst + swz(r, c16), gbase + (size_t)r * rowb + c16 * 16);
    }
}

__global__ __launch_bounds__(128, 2) void gemm_split_mma(
    const __nv_bfloat16* __restrict__ Ahi, const __nv_bfloat16* __restrict__ Alo,
    const __nv_bfloat16* __restrict__ Bhi, const __nv_bfloat16* __restrict__ Blo,
    float* __restrict__ C, int M, int N, int K) {
    extern __shared__ char smem[];
    const uint32_t sb = smem_u32(smem);
    const int tid = threadIdx.x, lane = tid & 31, wid = tid >> 5;
    const int wm = wid & 1, wn = wid >> 1;            // 2 x 2 warp grid, 64x64 tile
    const int m0 = blockIdx.y * 128, n0 = blockIdx.x * 128;
    const int nchunk = K >> 5;

    // ldmatrix lane addressing
    const int a_row = (lane & 7) + 8 * ((lane >> 3) & 1);
    const int a_c8  = lane >> 4;            // 0..1 (16B chunk within 32B k-step)
    const int b_row = (lane & 7) + 8 * (lane >> 4);
    const int b_c8  = (lane >> 3) & 1;

    const int arow = wm * 64 + a_row;       // +mt*16 phases don't change sel
    const int selA = (arow >> 1) & 3;
    const int brow = wn * 64 + b_row;
    const int selB = (brow >> 1) & 3;

    float acc[4][8][4];
#pragma unroll
    for (int i = 0; i < 4; i++)
#pragma unroll
        for (int j = 0; j < 8; j++)
#pragma unroll
            for (int r = 0; r < 4; r++) acc[i][j][r] = 0.f;

    // prologue
#pragma unroll
    for (int s = 0; s < GSTAGES; s++) {
        uint32_t st = sb + s * GSTAGE_BYTES;
        int k0 = s * 32;
        load_tile32(st,                  Ahi, m0, k0, K, tid);
        load_tile32(st + GMAT_BYTES,     Alo, m0, k0, K, tid);
        load_tile32(st + 2 * GMAT_BYTES, Bhi, n0, k0, K, tid);
        load_tile32(st + 3 * GMAT_BYTES, Blo, n0, k0, K, tid);
        CP_ASYNC_COMMIT();
    }

    for (int c = 0; c < nchunk; c++) {
        uint32_t st = sb + (c % GSTAGES) * GSTAGE_BYTES;
        CP_ASYNC_WAIT2();
        __syncthreads();

#pragma unroll
        for (int ks = 0; ks < 2; ks++) {     // k = 0, 16 within chunk
            const int ks2 = ks * 2;
            const uint32_t ca = (uint32_t)(((ks2 + a_c8) ^ selA) << 4);
            const uint32_t cb = (uint32_t)(((ks2 + b_c8) ^ selB) << 4);

            uint32_t ah[4][4], al[4][4];
#pragma unroll
            for (int mt = 0; mt < 4; mt++) {
                uint32_t ra = st + (uint32_t)((arow + mt * 16) * 64) + ca;
                ldsm4(ah[mt], ra);
                ldsm4(al[mt], ra + GMAT_BYTES);
            }
#pragma unroll
            for (int np = 0; np < 4; np++) {
                uint32_t bh[4], bl[4];
                uint32_t rb = st + 2 * GMAT_BYTES + (uint32_t)((brow + np * 16) * 64) + cb;
                ldsm4(bh, rb);
                ldsm4(bl, rb + GMAT_BYTES);
#pragma unroll
                for (int mt = 0; mt < 4; mt++)
#pragma unroll
                    for (int hf = 0; hf < 2; hf++) {
                        float* a4 = acc[mt][np * 2 + hf];
                        mma16816(a4, ah[mt], &bh[hf * 2]);   // hi*hi
                        mma16816(a4, ah[mt], &bl[hf * 2]);   // hi*lo
                        mma16816(a4, al[mt], &bh[hf * 2]);   // lo*hi
                    }
            }
        }
        __syncthreads();

        if (c + GSTAGES < nchunk) {
            int k0 = (c + GSTAGES) * 32;
            load_tile32(st,                  Ahi, m0, k0, K, tid);
            load_tile32(st + GMAT_BYTES,     Alo, m0, k0, K, tid);
            load_tile32(st + 2 * GMAT_BYTES, Bhi, n0, k0, K, tid);
            load_tile32(st + 3 * GMAT_BYTES, Blo, n0, k0, K, tid);
        }
        CP_ASYNC_COMMIT();
    }

    // epilogue
    const int crow = lane >> 2, ccol = (lane & 3) * 2;
#pragma unroll
    for (int mt = 0; mt < 4; mt++) {
        int rbase = m0 + wm * 64 + mt * 16 + crow;
#pragma unroll
        for (int nt = 0; nt < 8; nt++) {
            int cbase = n0 + wn * 64 + nt * 8 + ccol;
            float* d0 = C + (size_t)rbase * N + cbase;
            float* d1 = C + (size_t)(rbase + 8) * N + cbase;
            *(float2*)d0 = make_float2(acc[mt][nt][0], acc[mt][nt][1]);
            *(float2*)d1 = make_float2(acc[mt][nt][2], acc[mt][nt][3]);
        }
    }
}

// ================= split / transpose-split =================
__global__ __launch_bounds__(256) void split_kernel(const float* __restrict__ in,
                                                    __nv_bfloat16* __restrict__ hi,
                                                    __nv_bfloat16* __restrict__ lo, int n) {
    int i = blockIdx.x * blockDim.x + threadIdx.x;
    if (i >= n) return;
    float v = in[i];
    __nv_bfloat16 h = __float2bfloat16(v);
    hi[i] = h;
    lo[i] = __float2bfloat16(v - __bfloat162float(h));
}

// W: [K, N] fp32 -> Thi/Tlo: [N, K] bf16
__global__ __launch_bounds__(256) void tsplit_kernel(const float* __restrict__ W,
                                                     __nv_bfloat16* __restrict__ Thi,
                                                     __nv_bfloat16* __restrict__ Tlo,
                                                     int K, int N) {
    __shared__ float t[32][33];
    int n0 = blockIdx.x * 32, k0 = blockIdx.y * 32;
    int tx = threadIdx.x & 31, ty = threadIdx.x >> 5;  // 32x8
#pragma unroll
    for (int i = ty; i < 32; i += 8)
        t[i][tx] = W[(size_t)(k0 + i) * N + n0 + tx];
    __syncthreads();
#pragma unroll
    for (int i = ty; i < 32; i += 8) {
        float v = t[tx][i];  // k=k0+tx, n=n0+i
        __nv_bfloat16 h = __float2bfloat16(v);
        size_t oidx = (size_t)(n0 + i) * K + k0 + tx;
        Thi[oidx] = h;
        Tlo[oidx] = __float2bfloat16(v - __bfloat162float(h));
    }
}

// ---------------- RoPE (in place on q and k), q also scaled by DK^-1/2 ----------------
__global__ void rope_kernel(float* __restrict__ q, float* __restrict__ k) {
    int idx = blockIdx.x * blockDim.x + threadIdx.x;
    const int total = BB * TT * HH * (DKk / 2);
    if (idx >= total) return;
    int i = idx & 63;
    int h = (idx >> 6) & (HH - 1);
    int t = (idx >> 9) & (TT - 1);
    int b = idx >> 20;

    float inv = powf(10000.f, -(float)i * (1.0f / 64.0f));
    float f = (float)t * inv;
    float s, c;
    sincosf(f, &s, &c);

    size_t base = ((((size_t)b * TT + t) * HH + h) << 7);
    const float sc = 0.08838834764831845f;
    float q1 = q[base + i], q2 = q[base + 64 + i];
    q[base + i]      = (q1 * c - q2 * s) * sc;
    q[base + 64 + i] = (q2 * c + q1 * s) * sc;
    float k1 = k[base + i], k2 = k[base + 64 + i];
    k[base + i]      = k1 * c - k2 * s;
    k[base + 64 + i] = k2 * c + k1 * s;
}

// ---------------- chunked retention ----------------
#define RET_SMEM_FLOATS (128 * 65 + 2 * 64 * 129 + 2 * 64 * 65 + 3 * 64)

__global__ __launch_bounds__(256) void retention_kernel(const float* __restrict__ q,
                                                        const float* __restrict__ k,
                                                        const float* __restrict__ v,
                                                        float* __restrict__ o) {
    const int sl = blockIdx.x;
    const int h  = blockIdx.y;
    const int b  = blockIdx.z;
    const int tid = threadIdx.x;

    extern __shared__ float sm[];
    float* S    = sm;
    float* qs   = S + 128 * 65;
    float* ks   = qs + 64 * 129;
    float* vs   = ks + 64 * 129;
    float* at   = vs + 64 * 65;
    float* gpow = at + 64 * 65;
    float* decq = gpow + 64;
    float* deck = decq + 64;

    const float gamma = 1.0f - exp2f(-5.0f - (float)h);
    if (tid < 64) {
        gpow[tid] = powf(gamma, (float)tid);
        decq[tid] = powf(gamma, (float)(tid + 1));
        deck[tid] = powf(gamma, (float)(63 - tid));
    }
    const float gC = powf(gamma, 64.0f);

    for (int e = tid; e < 128 * 65; e += 256) S[e] = 0.f;
    __syncthreads();

    const int ti = tid >> 4;
    const int te = tid & 15;

    for (int n = 0; n < NCHUNK; n++) {
        const int t0 = n * CC;
        for (int e = tid; e < 64 * 128; e += 256) {
            int i = e >> 7, dk = e & 127;
            size_t gi = ((((size_t)b * TT + t0 + i) * HH + h) << 7) + dk;
            qs[i * 129 + dk] = q[gi];
            ks[i * 129 + dk] = k[gi];
        }
        for (int e = tid; e < 64 * 64; e += 256) {
            int i = e >> 6, ev = e & 63;
            size_t gi = (((size_t)b * TT + t0 + i) * HH + h) * DVv + sl * 64 + ev;
            vs[i * 65 + ev] = v[gi];
        }
        __syncthreads();

        {
            float acc[4][4];
#pragma unroll
            for (int a = 0; a < 4; a++)
#pragma unroll
                for (int bq = 0; bq < 4; bq++) acc[a][bq] = 0.f;
            for (int dk = 0; dk < 128; dk++) {
                float ra[4], rb[4];
#pragma unroll
                for (int ii = 0; ii < 4; ii++) ra[ii] = qs[(ti * 4 + ii) * 129 + dk];
#pragma unroll
                for (int jj = 0; jj < 4; jj++) rb[jj] = ks[(te * 4 + jj) * 129 + dk];
#pragma unroll
                for (int ii = 0; ii < 4; ii++)
#pragma unroll
                    for (int jj = 0; jj < 4; jj++) acc[ii][jj] += ra[ii] * rb[jj];
            }
#pragma unroll
            for (int ii = 0; ii < 4; ii++)
#pragma unroll
                for (int jj = 0; jj < 4; jj++) {
                    int i = ti * 4 + ii, j = te * 4 + jj;
                    at[i * 65 + j] = (i >= j) ? acc[ii][jj] * gpow[i - j] : 0.f;
                }
        }
        __syncthreads();

        {
            float aI[4][4], aS[4][4];
#pragma unroll
            for (int a = 0; a < 4; a++)
#pragma unroll
                for (int bq = 0; bq < 4; bq++) { aI[a][bq] = 0.f; aS[a][bq] = 0.f; }
            for (int j = 0; j < 64; j++) {
                float ra[4], rb[4];
#pragma unroll
                for (int ii = 0; ii < 4; ii++) ra[ii] = at[(ti * 4 + ii) * 65 + j];
#pragma unroll
                for (int ee = 0; ee < 4; ee++) rb[ee] = vs[j * 65 + te * 4 + ee];
#pragma unroll
                for (int ii = 0; ii < 4; ii++)
#pragma unroll
                    for (int ee = 0; ee < 4; ee++) aI[ii][ee] += ra[ii] * rb[ee];
            }
            for (int dk = 0; dk < 128; dk++) {
                float ra[4], rb[4];
#pragma unroll
                for (int ii = 0; ii < 4; ii++) ra[ii] = qs[(ti * 4 + ii) * 129 + dk];
#pragma unroll
                for (int ee = 0; ee < 4; ee++) rb[ee] = S[dk * 65 + te * 4 + ee];
#pragma unroll
                for (int ii = 0; ii < 4; ii++)
#pragma unroll
                    for (int ee = 0; ee < 4; ee++) aS[ii][ee] += ra[ii] * rb[ee];
            }
#pragma unroll
            for (int ii = 0; ii < 4; ii++) {
                int i = ti * 4 + ii;
                float dq = decq[i];
                size_t base = (((size_t)b * TT + t0 + i) * HH + h) * DVv + sl * 64 + te * 4;
#pragma unroll
                for (int ee = 0; ee < 4; ee++)
                    o[base + ee] = aI[ii][ee] + dq * aS[ii][ee];
            }
        }
        __syncthreads();

        {
            float acc[8][4];
#pragma unroll
            for (int a = 0; a < 8; a++)
#pragma unroll
                for (int bq = 0; bq < 4; bq++) acc[a][bq] = 0.f;
            for (int j = 0; j < 64; j++) {
                float dkj = deck[j];
                float ra[8], rb[4];
#pragma unroll
                for (int dd = 0; dd < 8; dd++) ra[dd] = ks[j * 129 + ti * 8 + dd] * dkj;
#pragma unroll
                for (int ee = 0; ee < 4; ee++) rb[ee] = vs[j * 65 + te * 4 + ee];
#pragma unroll
                for (int dd = 0; dd < 8; dd++)
#pragma unroll
                    for (int ee = 0; ee < 4; ee++) acc[dd][ee] += ra[dd] * rb[ee];
            }
#pragma unroll
            for (int dd = 0; dd < 8; dd++)
#pragma unroll
                for (int ee = 0; ee < 4; ee++) {
                    int dk = ti * 8 + dd, ev = te * 4 + ee;
                    S[dk * 65 + ev] = gC * S[dk * 65 + ev] + acc[dd][ee];
                }
        }
        __syncthreads();
    }
}

// ---------------- RMSNorm + swish gate + bf16 split (fused) ----------------
__global__ __launch_bounds__(256) void normgate_split_kernel(const float* __restrict__ o,
                                                             const float* __restrict__ g,
                                                             const float* __restrict__ norm_w,
                                                             __nv_bfloat16* __restrict__ ohi,
                                                             __nv_bfloat16* __restrict__ olo) {
    int warp = (blockIdx.x * blockDim.x + threadIdx.x) >> 5;
    int lane = threadIdx.x & 31;
    if (warp >= MROWS * HH) return;
    size_t base = (size_t)warp * DVv;

    float vals[8];
    float ss = 0.f;
#pragma unroll
    for (int r = 0; r < 8; r++) {
        vals[r] = o[base + lane + 32 * r];
        ss += vals[r] * vals[r];
    }
#pragma unroll
    for (int off = 16; off; off >>= 1) ss += __shfl_xor_sync(0xFFFFFFFFu, ss, off);
    float inv = rsqrtf(ss * (1.0f / 256.0f) + 1e-5f);

#pragma unroll
    for (int r = 0; r < 8; r++) {
        int ev = lane + 32 * r;
        float gv = g[base + ev];
        float sg = 1.f / (1.f + expf(-gv));
        float res = vals[r] * inv * norm_w[ev] * gv * sg;
        __nv_bfloat16 h = __float2bfloat16(res);
        ohi[base + ev] = h;
        olo[base + ev] = __float2bfloat16(res - __bfloat162float(h));
    }
}

// ---------------- launch ----------------
static void launch_gemm(const __nv_bfloat16* Ahi, const __nv_bfloat16* Alo,
                        const __nv_bfloat16* Bhi, const __nv_bfloat16* Blo,
                        float* C, int M, int N, int K) {
    gemm_split_mma<<<dim3(N / 128, M / 128), 128, GEMM_SMEM_BYTES>>>(Ahi, Alo, Bhi, Blo, C, M, N, K);
}

extern "C" void kernel_launch(void* const* d_in, const int* in_sizes, int n_in,
                              void* d_out, int out_size) {
    const float* x      = (const float*)d_in[0];
    const float* Wq     = (const float*)d_in[1];
    const float* Wk     = (const float*)d_in[2];
    const float* Wv     = (const float*)d_in[3];
    const float* Wg     = (const float*)d_in[4];
    const float* Wo     = (const float*)d_in[5];
    const float* norm_w = (const float*)d_in[6];
    float* out = (float*)d_out;

    float *q, *k, *v, *g, *o;
    cudaGetSymbolAddress((void**)&q, g_q);
    cudaGetSymbolAddress((void**)&k, g_k);
    cudaGetSymbolAddress((void**)&v, g_v);
    cudaGetSymbolAddress((void**)&g, g_g);
    cudaGetSymbolAddress((void**)&o, g_o);
    __nv_bfloat16 *xhi, *xlo, *ohi, *olo;
    __nv_bfloat16 *wqh, *wql, *wkh, *wkl, *wvh, *wvl, *wgh, *wgl, *woh, *wol;
    cudaGetSymbolAddress((void**)&xhi, g_xhi);
    cudaGetSymbolAddress((void**)&xlo, g_xlo);
    cudaGetSymbolAddress((void**)&ohi, g_ohi);
    cudaGetSymbolAddress((void**)&olo, g_olo);
    cudaGetSymbolAddress((void**)&wqh, g_wq_hi); cudaGetSymbolAddress((void**)&wql, g_wq_lo);
    cudaGetSymbolAddress((void**)&wkh, g_wk_hi); cudaGetSymbolAddress((void**)&wkl, g_wk_lo);
    cudaGetSymbolAddress((void**)&wvh, g_wv_hi); cudaGetSymbolAddress((void**)&wvl, g_wv_lo);
    cudaGetSymbolAddress((void**)&wgh, g_wg_hi); cudaGetSymbolAddress((void**)&wgl, g_wg_lo);
    cudaGetSymbolAddress((void**)&woh, g_wo_hi); cudaGetSymbolAddress((void**)&wol, g_wo_lo);

    const int ret_smem = RET_SMEM_FLOATS * sizeof(float);
    cudaFuncSetAttribute(retention_kernel, cudaFuncAttributeMaxDynamicSharedMemorySize, ret_smem);
    cudaFuncSetAttribute(gemm_split_mma, cudaFuncAttributeMaxDynamicSharedMemorySize, GEMM_SMEM_BYTES);

    // split inputs + transpose-split weights
    {
        int n = MROWS * DD;
        split_kernel<<<(n + 255) / 256, 256>>>(x, xhi, xlo, n);
    }
    tsplit_kernel<<<dim3(DD / 32, DD / 32), 256>>>(Wq, wqh, wql, DD, DD);
    tsplit_kernel<<<dim3(DD / 32, DD / 32), 256>>>(Wk, wkh, wkl, DD, DD);
    tsplit_kernel<<<dim3(2 * DD / 32, DD / 32), 256>>>(Wv, wvh, wvl, DD, 2 * DD);
    tsplit_kernel<<<dim3(2 * DD / 32, DD / 32), 256>>>(Wg, wgh, wgl, DD, 2 * DD);
    tsplit_kernel<<<dim3(DD / 32, 2 * DD / 32), 256>>>(Wo, woh, wol, 2 * DD, DD);

    // projections on tensor cores
    launch_gemm(xhi, xlo, wqh, wql, q, MROWS, DD, DD);
    launch_gemm(xhi, xlo, wkh, wkl, k, MROWS, DD, DD);
    launch_gemm(xhi, xlo, wvh, wvl, v, MROWS, 2 * DD, DD);
    launch_gemm(xhi, xlo, wgh, wgl, g, MROWS, 2 * DD, DD);

    // rope + scale
    {
        int total = BB * TT * HH * (DKk / 2);
        rope_kernel<<<(total + 255) / 256, 256>>>(q, k);
    }

    // chunked retention
    retention_kernel<<<dim3(DVv / 64, HH, BB), 256, ret_smem>>>(q, k, v, o);

    // rmsnorm + gate + split (fused)
    {
        int warps = MROWS * HH;
        normgate_split_kernel<<<(warps * 32 + 255) / 256, 256>>>(o, g, norm_w, ohi, olo);
    }

    // output projection on tensor cores
    launch_gemm(ohi, olo, woh, wol, out, MROWS, DD, 2 * DD);
}

// round 6
// speedup vs baseline: 2.3749x; 1.0487x over previous
#include <cuda_runtime.h>
#include <cuda_bf16.h>
#include <math.h>
#include <stdint.h>

// ---------------- problem constants ----------------
#define BB 4
#define TT 2048
#define DD 1024
#define HH 8
#define DKk 128
#define DVv 256
#define CC 64
#define NCHUNK (TT / CC)   // 32
#define MROWS (BB * TT)    // 8192
#define NBH (BB * HH)      // 32

// ---------------- scratch (no runtime allocation allowed) ----------------
__device__ float g_q[MROWS * HH * DKk];
__device__ float g_k[MROWS * HH * DKk];
__device__ float g_v[MROWS * HH * DVv];
__device__ float g_g[MROWS * HH * DVv];
__device__ float g_o[MROWS * HH * DVv];

// retention intermediates
__device__ float g_attn[NBH * NCHUNK * CC * CC];          // 16.8M floats
__device__ float g_kv[NBH * NCHUNK * DKk * DVv];          // 33.5M floats
__device__ float g_S[NBH * NCHUNK * DKk * DVv];           // 33.5M floats

// bf16 split operands
__device__ __nv_bfloat16 g_xhi[MROWS * DD];
__device__ __nv_bfloat16 g_xlo[MROWS * DD];
__device__ __nv_bfloat16 g_ohi[MROWS * HH * DVv];
__device__ __nv_bfloat16 g_olo[MROWS * HH * DVv];
// transposed weights [N, K]
__device__ __nv_bfloat16 g_wq_hi[DD * DD],       g_wq_lo[DD * DD];
__device__ __nv_bfloat16 g_wk_hi[DD * DD],       g_wk_lo[DD * DD];
__device__ __nv_bfloat16 g_wv_hi[2 * DD * DD],   g_wv_lo[2 * DD * DD];
__device__ __nv_bfloat16 g_wg_hi[2 * DD * DD],   g_wg_lo[2 * DD * DD];
__device__ __nv_bfloat16 g_wo_hi[2 * DD * DD],   g_wo_lo[2 * DD * DD];

// ================= PTX helpers (plain sm_80+ ISA only) =================
__device__ __forceinline__ uint32_t smem_u32(const void* p) {
    uint32_t a;
    asm("{ .reg .u64 t; cvta.to.shared.u64 t, %1; cvt.u32.u64 %0, t; }" : "=r"(a) : "l"(p));
    return a;
}
#define CP_ASYNC16(dst, src) \
    asm volatile("cp.async.cg.shared.global [%0], [%1], 16;" :: "r"(dst), "l"(src))
#define CP_ASYNC_COMMIT() asm volatile("cp.async.commit_group;" ::: "memory")
#define CP_ASYNC_WAIT2() asm volatile("cp.async.wait_group 2;" ::: "memory")

__device__ __forceinline__ void ldsm4(uint32_t* r, uint32_t addr) {
    asm volatile("ldmatrix.sync.aligned.m8n8.x4.shared.b16 {%0,%1,%2,%3}, [%4];"
        : "=r"(r[0]), "=r"(r[1]), "=r"(r[2]), "=r"(r[3]) : "r"(addr));
}
__device__ __forceinline__ void mma16816(float* c, const uint32_t* a, const uint32_t* b) {
    asm volatile("mma.sync.aligned.m16n8k16.row.col.f32.bf16.bf16.f32 "
        "{%0,%1,%2,%3}, {%4,%5,%6,%7}, {%8,%9}, {%0,%1,%2,%3};"
        : "+f"(c[0]), "+f"(c[1]), "+f"(c[2]), "+f"(c[3])
        : "r"(a[0]), "r"(a[1]), "r"(a[2]), "r"(a[3]), "r"(b[0]), "r"(b[1]));
}

// ================= split-bf16 tensor-core GEMM (unchanged from R5) ==========
#define GSTAGES 3
#define GMAT_BYTES (128 * 64)
#define GSTAGE_BYTES (4 * GMAT_BYTES)
#define GEMM_SMEM_BYTES (GSTAGES * GSTAGE_BYTES)

__device__ __forceinline__ uint32_t swz(int row, int c16) {
    return (uint32_t)(row * 64 + ((c16 ^ ((row >> 1) & 3)) << 4));
}

__device__ __forceinline__ void load_tile32(uint32_t dst, const __nv_bfloat16* src,
                                            int row0, int k0, int ldk, int tid) {
    const char* gbase = (const char*)(src + (size_t)row0 * ldk + k0);
    const size_t rowb = (size_t)ldk * 2;
#pragma unroll
    for (int j = 0; j < 4; j++) {
        int e = tid + j * 128;
        int r = e >> 2, c16 = e & 3;
        CP_ASYNC16(dst + swz(r, c16), gbase + (size_t)r * rowb + c16 * 16);
    }
}

__global__ __launch_bounds__(128, 2) void gemm_split_mma(
    const __nv_bfloat16* __restrict__ Ahi, const __nv_bfloat16* __restrict__ Alo,
    const __nv_bfloat16* __restrict__ Bhi, const __nv_bfloat16* __restrict__ Blo,
    float* __restrict__ C, int M, int N, int K) {
    extern __shared__ char smem[];
    const uint32_t sb = smem_u32(smem);
    const int tid = threadIdx.x, lane = tid & 31, wid = tid >> 5;
    const int wm = wid & 1, wn = wid >> 1;
    const int m0 = blockIdx.y * 128, n0 = blockIdx.x * 128;
    const int nchunk = K >> 5;

    const int a_row = (lane & 7) + 8 * ((lane >> 3) & 1);
    const int a_c8  = lane >> 4;
    const int b_row = (lane & 7) + 8 * (lane >> 4);
    const int b_c8  = (lane >> 3) & 1;

    const int arow = wm * 64 + a_row;
    const int selA = (arow >> 1) & 3;
    const int brow = wn * 64 + b_row;
    const int selB = (brow >> 1) & 3;

    float acc[4][8][4];
#pragma unroll
    for (int i = 0; i < 4; i++)
#pragma unroll
        for (int j = 0; j < 8; j++)
#pragma unroll
            for (int r = 0; r < 4; r++) acc[i][j][r] = 0.f;

#pragma unroll
    for (int s = 0; s < GSTAGES; s++) {
        uint32_t st = sb + s * GSTAGE_BYTES;
        int k0 = s * 32;
        load_tile32(st,                  Ahi, m0, k0, K, tid);
        load_tile32(st + GMAT_BYTES,     Alo, m0, k0, K, tid);
        load_tile32(st + 2 * GMAT_BYTES, Bhi, n0, k0, K, tid);
        load_tile32(st + 3 * GMAT_BYTES, Blo, n0, k0, K, tid);
        CP_ASYNC_COMMIT();
    }

    for (int c = 0; c < nchunk; c++) {
        uint32_t st = sb + (c % GSTAGES) * GSTAGE_BYTES;
        CP_ASYNC_WAIT2();
        __syncthreads();

#pragma unroll
        for (int ks = 0; ks < 2; ks++) {
            const int ks2 = ks * 2;
            const uint32_t ca = (uint32_t)(((ks2 + a_c8) ^ selA) << 4);
            const uint32_t cb = (uint32_t)(((ks2 + b_c8) ^ selB) << 4);

            uint32_t ah[4][4], al[4][4];
#pragma unroll
            for (int mt = 0; mt < 4; mt++) {
                uint32_t ra = st + (uint32_t)((arow + mt * 16) * 64) + ca;
                ldsm4(ah[mt], ra);
                ldsm4(al[mt], ra + GMAT_BYTES);
            }
#pragma unroll
            for (int np = 0; np < 4; np++) {
                uint32_t bh[4], bl[4];
                uint32_t rb = st + 2 * GMAT_BYTES + (uint32_t)((brow + np * 16) * 64) + cb;
                ldsm4(bh, rb);
                ldsm4(bl, rb + GMAT_BYTES);
#pragma unroll
                for (int mt = 0; mt < 4; mt++)
#pragma unroll
                    for (int hf = 0; hf < 2; hf++) {
                        float* a4 = acc[mt][np * 2 + hf];
                        mma16816(a4, ah[mt], &bh[hf * 2]);
                        mma16816(a4, ah[mt], &bl[hf * 2]);
                        mma16816(a4, al[mt], &bh[hf * 2]);
                    }
            }
        }
        __syncthreads();

        if (c + GSTAGES < nchunk) {
            int k0 = (c + GSTAGES) * 32;
            load_tile32(st,                  Ahi, m0, k0, K, tid);
            load_tile32(st + GMAT_BYTES,     Alo, m0, k0, K, tid);
            load_tile32(st + 2 * GMAT_BYTES, Bhi, n0, k0, K, tid);
            load_tile32(st + 3 * GMAT_BYTES, Blo, n0, k0, K, tid);
        }
        CP_ASYNC_COMMIT();
    }

    const int crow = lane >> 2, ccol = (lane & 3) * 2;
#pragma unroll
    for (int mt = 0; mt < 4; mt++) {
        int rbase = m0 + wm * 64 + mt * 16 + crow;
#pragma unroll
        for (int nt = 0; nt < 8; nt++) {
            int cbase = n0 + wn * 64 + nt * 8 + ccol;
            float* d0 = C + (size_t)rbase * N + cbase;
            float* d1 = C + (size_t)(rbase + 8) * N + cbase;
            *(float2*)d0 = make_float2(acc[mt][nt][0], acc[mt][nt][1]);
            *(float2*)d1 = make_float2(acc[mt][nt][2], acc[mt][nt][3]);
        }
    }
}

// ================= split / transpose-split =================
__global__ __launch_bounds__(256) void split_kernel(const float* __restrict__ in,
                                                    __nv_bfloat16* __restrict__ hi,
                                                    __nv_bfloat16* __restrict__ lo, int n) {
    int i = blockIdx.x * blockDim.x + threadIdx.x;
    if (i >= n) return;
    float v = in[i];
    __nv_bfloat16 h = __float2bfloat16(v);
    hi[i] = h;
    lo[i] = __float2bfloat16(v - __bfloat162float(h));
}

__global__ __launch_bounds__(256) void tsplit_kernel(const float* __restrict__ W,
                                                     __nv_bfloat16* __restrict__ Thi,
                                                     __nv_bfloat16* __restrict__ Tlo,
                                                     int K, int N) {
    __shared__ float t[32][33];
    int n0 = blockIdx.x * 32, k0 = blockIdx.y * 32;
    int tx = threadIdx.x & 31, ty = threadIdx.x >> 5;
#pragma unroll
    for (int i = ty; i < 32; i += 8)
        t[i][tx] = W[(size_t)(k0 + i) * N + n0 + tx];
    __syncthreads();
#pragma unroll
    for (int i = ty; i < 32; i += 8) {
        float v = t[tx][i];
        __nv_bfloat16 h = __float2bfloat16(v);
        size_t oidx = (size_t)(n0 + i) * K + k0 + tx;
        Thi[oidx] = h;
        Tlo[oidx] = __float2bfloat16(v - __bfloat162float(h));
    }
}

// ---------------- RoPE (in place on q and k), q also scaled by DK^-1/2 ------
__global__ void rope_kernel(float* __restrict__ q, float* __restrict__ k) {
    int idx = blockIdx.x * blockDim.x + threadIdx.x;
    const int total = BB * TT * HH * (DKk / 2);
    if (idx >= total) return;
    int i = idx & 63;
    int h = (idx >> 6) & (HH - 1);
    int t = (idx >> 9) & (TT - 1);
    int b = idx >> 20;

    float inv = powf(10000.f, -(float)i * (1.0f / 64.0f));
    float f = (float)t * inv;
    float s, c;
    sincosf(f, &s, &c);

    size_t base = ((((size_t)b * TT + t) * HH + h) << 7);
    const float sc = 0.08838834764831845f;
    float q1 = q[base + i], q2 = q[base + 64 + i];
    q[base + i]      = (q1 * c - q2 * s) * sc;
    q[base + 64 + i] = (q2 * c + q1 * s) * sc;
    float k1 = k[base + i], k2 = k[base + 64 + i];
    k[base + i]      = k1 * c - k2 * s;
    k[base + 64 + i] = k2 * c + k1 * s;
}

// ================= retention, 4 parallel phases =================

// Phase A: attn[b,h,n] = (q_chunk @ k_chunk^T) * M   -> g_attn
// grid (NCHUNK, HH, BB), 256 threads
#define ATTN_SMEM ((2 * 64 * 129 + 64) * 4)
__global__ __launch_bounds__(256) void ret_attn_kernel(const float* __restrict__ q,
                                                       const float* __restrict__ k,
                                                       float* __restrict__ attn_out) {
    const int n = blockIdx.x, h = blockIdx.y, b = blockIdx.z;
    const int tid = threadIdx.x;
    extern __shared__ float sm[];
    float* qs   = sm;              // 64*129
    float* ks   = qs + 64 * 129;   // 64*129
    float* gpow = ks + 64 * 129;   // 64

    const float gamma = 1.0f - exp2f(-5.0f - (float)h);
    if (tid < 64) gpow[tid] = powf(gamma, (float)tid);

    const int t0 = n * CC;
    for (int e = tid; e < 64 * 128; e += 256) {
        int i = e >> 7, dk = e & 127;
        size_t gi = ((((size_t)b * TT + t0 + i) * HH + h) << 7) + dk;
        qs[i * 129 + dk] = q[gi];
        ks[i * 129 + dk] = k[gi];
    }
    __syncthreads();

    const int ti = tid >> 4, te = tid & 15;
    float acc[4][4];
#pragma unroll
    for (int a = 0; a < 4; a++)
#pragma unroll
        for (int bq = 0; bq < 4; bq++) acc[a][bq] = 0.f;
    for (int dk = 0; dk < 128; dk++) {
        float ra[4], rb[4];
#pragma unroll
        for (int ii = 0; ii < 4; ii++) ra[ii] = qs[(ti * 4 + ii) * 129 + dk];
#pragma unroll
        for (int jj = 0; jj < 4; jj++) rb[jj] = ks[(te * 4 + jj) * 129 + dk];
#pragma unroll
        for (int ii = 0; ii < 4; ii++)
#pragma unroll
            for (int jj = 0; jj < 4; jj++) acc[ii][jj] += ra[ii] * rb[jj];
    }

    float* dst = attn_out + ((((size_t)b * HH + h) * NCHUNK + n) << 12);
#pragma unroll
    for (int ii = 0; ii < 4; ii++) {
        int i = ti * 4 + ii;
        float4 w;
        float* wp = &w.x;
#pragma unroll
        for (int jj = 0; jj < 4; jj++) {
            int j = te * 4 + jj;
            wp[jj] = (i >= j) ? acc[ii][jj] * gpow[i - j] : 0.f;
        }
        *(float4*)(dst + i * 64 + te * 4) = w;
    }
}

// Phase B: kv[b,h,n] = (k*deck)^T @ v   -> g_kv   (per DV slice of 64)
// grid (4*NCHUNK, HH, BB), 256 threads
#define KV_SMEM ((64 * 129 + 64 * 65 + 64) * 4)
__global__ __launch_bounds__(256) void ret_kv_kernel(const float* __restrict__ k,
                                                     const float* __restrict__ v,
                                                     float* __restrict__ kv_out) {
    const int sl = blockIdx.x & 3, n = blockIdx.x >> 2;
    const int h = blockIdx.y, b = blockIdx.z;
    const int tid = threadIdx.x;
    extern __shared__ float sm[];
    float* ks   = sm;              // 64*129
    float* vs   = ks + 64 * 129;   // 64*65  (pre-scaled by deck)
    float* deck = vs + 64 * 65;    // 64

    const float gamma = 1.0f - exp2f(-5.0f - (float)h);
    if (tid < 64) deck[tid] = powf(gamma, (float)(63 - tid));
    __syncthreads();

    const int t0 = n * CC;
    for (int e = tid; e < 64 * 128; e += 256) {
        int i = e >> 7, dk = e & 127;
        size_t gi = ((((size_t)b * TT + t0 + i) * HH + h) << 7) + dk;
        ks[i * 129 + dk] = k[gi];
    }
    for (int e = tid; e < 64 * 64; e += 256) {
        int i = e >> 6, ev = e & 63;
        size_t gi = (((size_t)b * TT + t0 + i) * HH + h) * DVv + sl * 64 + ev;
        vs[i * 65 + ev] = v[gi] * deck[i];
    }
    __syncthreads();

    const int ti = tid >> 4, te = tid & 15;   // dk group of 8, ev group of 4
    float acc[8][4];
#pragma unroll
    for (int a = 0; a < 8; a++)
#pragma unroll
        for (int bq = 0; bq < 4; bq++) acc[a][bq] = 0.f;
    for (int j = 0; j < 64; j++) {
        float ra[8], rb[4];
#pragma unroll
        for (int dd = 0; dd < 8; dd++) ra[dd] = ks[j * 129 + ti * 8 + dd];
#pragma unroll
        for (int ee = 0; ee < 4; ee++) rb[ee] = vs[j * 65 + te * 4 + ee];
#pragma unroll
        for (int dd = 0; dd < 8; dd++)
#pragma unroll
            for (int ee = 0; ee < 4; ee++) acc[dd][ee] += ra[dd] * rb[ee];
    }

    float* dst = kv_out + ((((size_t)b * HH + h) * NCHUNK + n) * DKk) * DVv + sl * 64;
#pragma unroll
    for (int dd = 0; dd < 8; dd++) {
        int dk = ti * 8 + dd;
        *(float4*)(dst + (size_t)dk * DVv + te * 4) =
            make_float4(acc[dd][0], acc[dd][1], acc[dd][2], acc[dd][3]);
    }
}

// Phase C: S_pre[n] = gC*S_pre[n-1] + kv[n-1], S_pre[0] = 0  -> g_S
// one thread per (bh, dk, ev); grid 4096 x 256
__global__ __launch_bounds__(256) void ret_scan_kernel(const float* __restrict__ kv,
                                                       float* __restrict__ Spre) {
    const int idx = blockIdx.x * 256 + threadIdx.x;   // < 32*128*256
    const int bh  = idx >> 15;
    const int pos = idx & 32767;
    const int h   = bh & (HH - 1);
    const float gamma = 1.0f - exp2f(-5.0f - (float)h);
    const float gC = powf(gamma, 64.0f);

    const size_t base = (size_t)bh * NCHUNK * 32768 + pos;
    float s = 0.f;
    Spre[base] = 0.f;
    for (int n = 1; n < NCHUNK; n++) {
        s = gC * s + kv[base + (size_t)(n - 1) * 32768];
        Spre[base + (size_t)n * 32768] = s;
    }
}

// Phase D: o = attn @ v + decq * (q @ S_pre)   (per DV slice of 64)
// grid (4*NCHUNK, HH, BB), 256 threads
#define OUT_SMEM ((64 * 65 + 64 * 65 + 64 * 129 + 128 * 65 + 64) * 4)
__global__ __launch_bounds__(256) void ret_out_kernel(const float* __restrict__ q,
                                                      const float* __restrict__ v,
                                                      const float* __restrict__ attn,
                                                      const float* __restrict__ Spre,
                                                      float* __restrict__ o) {
    const int sl = blockIdx.x & 3, n = blockIdx.x >> 2;
    const int h = blockIdx.y, b = blockIdx.z;
    const int tid = threadIdx.x;
    extern __shared__ float sm[];
    float* at   = sm;               // 64*65
    float* vs   = at + 64 * 65;     // 64*65
    float* qs   = vs + 64 * 65;     // 64*129
    float* Ss   = qs + 64 * 129;    // 128*65
    float* decq = Ss + 128 * 65;    // 64

    const float gamma = 1.0f - exp2f(-5.0f - (float)h);
    if (tid < 64) decq[tid] = powf(gamma, (float)(tid + 1));

    const int t0 = n * CC;
    const size_t bh = (size_t)b * HH + h;
    const float* asrc = attn + ((bh * NCHUNK + n) << 12);
    for (int e = tid; e < 64 * 64; e += 256) {
        int i = e >> 6, j = e & 63;
        at[i * 65 + j] = asrc[e];
        size_t gi = (((size_t)b * TT + t0 + i) * HH + h) * DVv + sl * 64 + j;
        vs[i * 65 + j] = v[gi];
    }
    for (int e = tid; e < 64 * 128; e += 256) {
        int i = e >> 7, dk = e & 127;
        size_t gi = ((((size_t)b * TT + t0 + i) * HH + h) << 7) + dk;
        qs[i * 129 + dk] = q[gi];
    }
    const float* ssrc = Spre + ((bh * NCHUNK + n) * DKk) * DVv + sl * 64;
    for (int e = tid; e < 128 * 64; e += 256) {
        int dk = e >> 6, ev = e & 63;
        Ss[dk * 65 + ev] = ssrc[(size_t)dk * DVv + ev];
    }
    __syncthreads();

    const int ti = tid >> 4, te = tid & 15;
    float aI[4][4], aS[4][4];
#pragma unroll
    for (int a = 0; a < 4; a++)
#pragma unroll
        for (int bq = 0; bq < 4; bq++) { aI[a][bq] = 0.f; aS[a][bq] = 0.f; }

    for (int j = 0; j < 64; j++) {
        float ra[4], rb[4];
#pragma unroll
        for (int ii = 0; ii < 4; ii++) ra[ii] = at[(ti * 4 + ii) * 65 + j];
#pragma unroll
        for (int ee = 0; ee < 4; ee++) rb[ee] = vs[j * 65 + te * 4 + ee];
#pragma unroll
        for (int ii = 0; ii < 4; ii++)
#pragma unroll
            for (int ee = 0; ee < 4; ee++) aI[ii][ee] += ra[ii] * rb[ee];
    }
    for (int dk = 0; dk < 128; dk++) {
        float ra[4], rb[4];
#pragma unroll
        for (int ii = 0; ii < 4; ii++) ra[ii] = qs[(ti * 4 + ii) * 129 + dk];
#pragma unroll
        for (int ee = 0; ee < 4; ee++) rb[ee] = Ss[dk * 65 + te * 4 + ee];
#pragma unroll
        for (int ii = 0; ii < 4; ii++)
#pragma unroll
            for (int ee = 0; ee < 4; ee++) aS[ii][ee] += ra[ii] * rb[ee];
    }

#pragma unroll
    for (int ii = 0; ii < 4; ii++) {
        int i = ti * 4 + ii;
        float dq = decq[i];
        size_t base = (((size_t)b * TT + t0 + i) * HH + h) * DVv + sl * 64 + te * 4;
        *(float4*)(&o[base]) = make_float4(aI[ii][0] + dq * aS[ii][0],
                                           aI[ii][1] + dq * aS[ii][1],
                                           aI[ii][2] + dq * aS[ii][2],
                                           aI[ii][3] + dq * aS[ii][3]);
    }
}

// ---------------- RMSNorm + swish gate + bf16 split (fused) ----------------
__global__ __launch_bounds__(256) void normgate_split_kernel(const float* __restrict__ o,
                                                             const float* __restrict__ g,
                                                             const float* __restrict__ norm_w,
                                                             __nv_bfloat16* __restrict__ ohi,
                                                             __nv_bfloat16* __restrict__ olo) {
    int warp = (blockIdx.x * blockDim.x + threadIdx.x) >> 5;
    int lane = threadIdx.x & 31;
    if (warp >= MROWS * HH) return;
    size_t base = (size_t)warp * DVv;

    float vals[8];
    float ss = 0.f;
#pragma unroll
    for (int r = 0; r < 8; r++) {
        vals[r] = o[base + lane + 32 * r];
        ss += vals[r] * vals[r];
    }
#pragma unroll
    for (int off = 16; off; off >>= 1) ss += __shfl_xor_sync(0xFFFFFFFFu, ss, off);
    float inv = rsqrtf(ss * (1.0f / 256.0f) + 1e-5f);

#pragma unroll
    for (int r = 0; r < 8; r++) {
        int ev = lane + 32 * r;
        float gv = g[base + ev];
        float sg = 1.f / (1.f + expf(-gv));
        float res = vals[r] * inv * norm_w[ev] * gv * sg;
        __nv_bfloat16 h = __float2bfloat16(res);
        ohi[base + ev] = h;
        olo[base + ev] = __float2bfloat16(res - __bfloat162float(h));
    }
}

// ---------------- launch ----------------
static void launch_gemm(const __nv_bfloat16* Ahi, const __nv_bfloat16* Alo,
                        const __nv_bfloat16* Bhi, const __nv_bfloat16* Blo,
                        float* C, int M, int N, int K) {
    gemm_split_mma<<<dim3(N / 128, M / 128), 128, GEMM_SMEM_BYTES>>>(Ahi, Alo, Bhi, Blo, C, M, N, K);
}

extern "C" void kernel_launch(void* const* d_in, const int* in_sizes, int n_in,
                              void* d_out, int out_size) {
    const float* x      = (const float*)d_in[0];
    const float* Wq     = (const float*)d_in[1];
    const float* Wk     = (const float*)d_in[2];
    const float* Wv     = (const float*)d_in[3];
    const float* Wg     = (const float*)d_in[4];
    const float* Wo     = (const float*)d_in[5];
    const float* norm_w = (const float*)d_in[6];
    float* out = (float*)d_out;

    float *q, *k, *v, *g, *o, *attn, *kv, *S;
    cudaGetSymbolAddress((void**)&q, g_q);
    cudaGetSymbolAddress((void**)&k, g_k);
    cudaGetSymbolAddress((void**)&v, g_v);
    cudaGetSymbolAddress((void**)&g, g_g);
    cudaGetSymbolAddress((void**)&o, g_o);
    cudaGetSymbolAddress((void**)&attn, g_attn);
    cudaGetSymbolAddress((void**)&kv, g_kv);
    cudaGetSymbolAddress((void**)&S, g_S);
    __nv_bfloat16 *xhi, *xlo, *ohi, *olo;
    __nv_bfloat16 *wqh, *wql, *wkh, *wkl, *wvh, *wvl, *wgh, *wgl, *woh, *wol;
    cudaGetSymbolAddress((void**)&xhi, g_xhi);
    cudaGetSymbolAddress((void**)&xlo, g_xlo);
    cudaGetSymbolAddress((void**)&ohi, g_ohi);
    cudaGetSymbolAddress((void**)&olo, g_olo);
    cudaGetSymbolAddress((void**)&wqh, g_wq_hi); cudaGetSymbolAddress((void**)&wql, g_wq_lo);
    cudaGetSymbolAddress((void**)&wkh, g_wk_hi); cudaGetSymbolAddress((void**)&wkl, g_wk_lo);
    cudaGetSymbolAddress((void**)&wvh, g_wv_hi); cudaGetSymbolAddress((void**)&wvl, g_wv_lo);
    cudaGetSymbolAddress((void**)&wgh, g_wg_hi); cudaGetSymbolAddress((void**)&wgl, g_wg_lo);
    cudaGetSymbolAddress((void**)&woh, g_wo_hi); cudaGetSymbolAddress((void**)&wol, g_wo_lo);

    cudaFuncSetAttribute(gemm_split_mma, cudaFuncAttributeMaxDynamicSharedMemorySize, GEMM_SMEM_BYTES);
    cudaFuncSetAttribute(ret_attn_kernel, cudaFuncAttributeMaxDynamicSharedMemorySize, ATTN_SMEM);
    cudaFuncSetAttribute(ret_kv_kernel, cudaFuncAttributeMaxDynamicSharedMemorySize, KV_SMEM);
    cudaFuncSetAttribute(ret_out_kernel, cudaFuncAttributeMaxDynamicSharedMemorySize, OUT_SMEM);

    // split inputs + transpose-split weights
    {
        int n = MROWS * DD;
        split_kernel<<<(n + 255) / 256, 256>>>(x, xhi, xlo, n);
    }
    tsplit_kernel<<<dim3(DD / 32, DD / 32), 256>>>(Wq, wqh, wql, DD, DD);
    tsplit_kernel<<<dim3(DD / 32, DD / 32), 256>>>(Wk, wkh, wkl, DD, DD);
    tsplit_kernel<<<dim3(2 * DD / 32, DD / 32), 256>>>(Wv, wvh, wvl, DD, 2 * DD);
    tsplit_kernel<<<dim3(2 * DD / 32, DD / 32), 256>>>(Wg, wgh, wgl, DD, 2 * DD);
    tsplit_kernel<<<dim3(DD / 32, 2 * DD / 32), 256>>>(Wo, woh, wol, 2 * DD, DD);

    // projections on tensor cores
    launch_gemm(xhi, xlo, wqh, wql, q, MROWS, DD, DD);
    launch_gemm(xhi, xlo, wkh, wkl, k, MROWS, DD, DD);
    launch_gemm(xhi, xlo, wvh, wvl, v, MROWS, 2 * DD, DD);
    launch_gemm(xhi, xlo, wgh, wgl, g, MROWS, 2 * DD, DD);

    // rope + scale
    {
        int total = BB * TT * HH * (DKk / 2);
        rope_kernel<<<(total + 255) / 256, 256>>>(q, k);
    }

    // retention: 4 parallel phases
    ret_attn_kernel<<<dim3(NCHUNK, HH, BB), 256, ATTN_SMEM>>>(q, k, attn);
    ret_kv_kernel<<<dim3(4 * NCHUNK, HH, BB), 256, KV_SMEM>>>(k, v, kv);
    ret_scan_kernel<<<(NBH * DKk * DVv) / 256, 256>>>(kv, S);
    ret_out_kernel<<<dim3(4 * NCHUNK, HH, BB), 256, OUT_SMEM>>>(q, v, attn, S, o);

    // rmsnorm + gate + split (fused)
    {
        int warps = MROWS * HH;
        normgate_split_kernel<<<(warps * 32 + 255) / 256, 256>>>(o, g, norm_w, ohi, olo);
    }

    // output projection on tensor cores
    launch_gemm(ohi, olo, woh, wol, out, MROWS, DD, 2 * DD);
}